// round 9
// baseline (speedup 1.0000x reference)
#include <cuda_runtime.h>
#include <cuda_bf16.h>
#include <math.h>

#define NN 100000
#define EE 800000

// ---------------- scratch (device globals; no allocations) ----------------
__device__ __nv_bfloat16 g_qb[NN * 224];    // bf16 q cache [N, HC]
__device__ __nv_bfloat16 g_kb[NN * 224];    // bf16 k cache [N, HC]
__device__ float g_vs[NN * 448];            // fp32 v|skip  [N, 2*HC]
__device__ float g_h1[NN * 224];
__device__ float g_h2[NN * 128];
__device__ float g_wp[204800];              // packed weights, 3 layers
__device__ float g_bp[1664];                // packed biases
// CSR scratch
__device__ int g_cnt[NN];
__device__ int g_row[NN + 1];
__device__ int g_cur[NN];
__device__ int g_bsum[256];
__device__ int g_boff[256];
__device__ int g_csrc[EE];

// ---------------- helpers ---------------------------------------------------
__device__ __forceinline__ void split_pack(float a, float b, unsigned& hi, unsigned& lo)
{
    __nv_bfloat16 ha = __float2bfloat16(a);
    __nv_bfloat16 hb = __float2bfloat16(b);
    __nv_bfloat16 la = __float2bfloat16(a - __bfloat162float(ha));
    __nv_bfloat16 lb = __float2bfloat16(b - __bfloat162float(hb));
    __nv_bfloat162 h2 = __halves2bfloat162(ha, hb);
    __nv_bfloat162 l2 = __halves2bfloat162(la, lb);
    hi = *(unsigned*)&h2;
    lo = *(unsigned*)&l2;
}

__device__ __forceinline__ void mma_bf16(float4& d, const unsigned a[4], const unsigned b[2])
{
    asm volatile("mma.sync.aligned.m16n8k16.row.col.f32.bf16.bf16.f32 "
                 "{%0,%1,%2,%3}, {%4,%5,%6,%7}, {%8,%9}, {%0,%1,%2,%3};"
                 : "+f"(d.x), "+f"(d.y), "+f"(d.z), "+f"(d.w)
                 : "r"(a[0]), "r"(a[1]), "r"(a[2]), "r"(a[3]),
                   "r"(b[0]), "r"(b[1]));
}

__device__ __forceinline__ void ldsm4(unsigned a[4], unsigned addr)
{
    asm volatile("ldmatrix.sync.aligned.m8n8.x4.shared.b16 {%0,%1,%2,%3}, [%4];"
                 : "=r"(a[0]), "=r"(a[1]), "=r"(a[2]), "=r"(a[3]) : "r"(addr));
}

__device__ __forceinline__ float2 bf2f(unsigned u)
{
    return __bfloat1622float2(*reinterpret_cast<__nv_bfloat162*>(&u));
}

// =====================================================================
// Weight pack: Wp[kk][j*HC + c] = Wj[kk][c]; bp[j*HC + c] = bj[c]
// =====================================================================
__global__ void pack_w(const float* __restrict__ Wq, const float* __restrict__ Wk,
                       const float* __restrict__ Wv, const float* __restrict__ Ws,
                       const float* __restrict__ bq, const float* __restrict__ bk,
                       const float* __restrict__ bv, const float* __restrict__ bs,
                       float* __restrict__ Wp, float* __restrict__ bp,
                       int din, int HC)
{
    int i = blockIdx.x * blockDim.x + threadIdx.x;
    int tot = din * 4 * HC;
    if (i < tot) {
        int kk  = i / (4 * HC);
        int rem = i - kk * 4 * HC;
        int j   = rem / HC;
        int c   = rem - j * HC;
        const float* Wj = (j == 0) ? Wq : (j == 1) ? Wk : (j == 2) ? Wv : Ws;
        Wp[i] = Wj[kk * HC + c];
    }
    if (i < 4 * HC) {
        int j = i / HC, c = i - j * HC;
        const float* bj = (j == 0) ? bq : (j == 1) ? bk : (j == 2) ? bv : bs;
        bp[i] = bj[c];
    }
}

// =====================================================================
// GEMM: [N,din] @ Wp[din,dout] + bp, dout = 4*HC (regions q|k|v|s).
// q,k written as bf16 caches; v,skip written fp32 to vs[N,2HC].
// Single-buffer smem (round-6 mainloop), ldmatrix A fragments.
// =====================================================================
__global__ void __launch_bounds__(256, 2)
gemm_bf16s(const float* __restrict__ X, const float* __restrict__ W,
           const float* __restrict__ bias,
           __nv_bfloat16* __restrict__ qb, __nv_bfloat16* __restrict__ kbuf,
           float* __restrict__ vs,
           int N, int din, int dout)
{
    constexpr int BN   = 128;
    constexpr int BSTR = BN + 8;

    __shared__ unsigned sAhi[128][12];
    __shared__ unsigned sAlo[128][12];
    __shared__ unsigned sBhi[8][BSTR];
    __shared__ unsigned sBlo[8][BSTR];

    const int tid  = threadIdx.x;
    const int lane = tid & 31;
    const int warp = tid >> 5;
    const int wm   = (warp & 1) * 64;
    const int wn   = (warp >> 1) * 32;
    const int m0   = blockIdx.x * 128;
    const int n0   = blockIdx.y * BN;
    const int HC   = dout >> 2;

    const int xr  = tid >> 1;
    const int xk  = (tid & 1) * 8;
    const int bpr = tid >> 5;
    const int bn0 = (tid & 31) * 4;

    float4 xreg0, xreg1, wreg0, wreg1;

    auto load_g = [&](int kb_) {
        int row = m0 + xr;
        if (row < N) {
            xreg0 = *(const float4*)&X[(size_t)row * din + kb_ + xk];
            xreg1 = *(const float4*)&X[(size_t)row * din + kb_ + xk + 4];
        } else {
            xreg0 = make_float4(0.f, 0.f, 0.f, 0.f);
            xreg1 = xreg0;
        }
        int col = n0 + bn0;
        wreg0 = *(const float4*)&W[(size_t)(kb_ + 2 * bpr) * dout + col];
        wreg1 = *(const float4*)&W[(size_t)(kb_ + 2 * bpr + 1) * dout + col];
    };

    auto store_smem = [&]() {
        uint4 hi4, lo4;
        split_pack(xreg0.x, xreg0.y, hi4.x, lo4.x);
        split_pack(xreg0.z, xreg0.w, hi4.y, lo4.y);
        split_pack(xreg1.x, xreg1.y, hi4.z, lo4.z);
        split_pack(xreg1.z, xreg1.w, hi4.w, lo4.w);
        *(uint4*)&sAhi[xr][xk >> 1] = hi4;
        *(uint4*)&sAlo[xr][xk >> 1] = lo4;
        split_pack(wreg0.x, wreg1.x, hi4.x, lo4.x);
        split_pack(wreg0.y, wreg1.y, hi4.y, lo4.y);
        split_pack(wreg0.z, wreg1.z, hi4.z, lo4.z);
        split_pack(wreg0.w, wreg1.w, hi4.w, lo4.w);
        *(uint4*)&sBhi[bpr][bn0] = hi4;
        *(uint4*)&sBlo[bpr][bn0] = lo4;
    };

    float4 d[4][4];
    #pragma unroll
    for (int i = 0; i < 4; i++)
        #pragma unroll
        for (int j = 0; j < 4; j++) d[i][j] = make_float4(0.f, 0.f, 0.f, 0.f);

    const int tg  = lane & 3;
    const int gid = lane >> 2;

    const int arow = (lane & 7) + ((lane >> 3) & 1) * 8;
    const int akp  = (lane >> 4) * 4;
    const unsigned offA = ((wm + arow) * 12 + akp) * 4;
    const unsigned addrAhi = (unsigned)__cvta_generic_to_shared(&sAhi[0][0]) + offA;
    const unsigned addrAlo = (unsigned)__cvta_generic_to_shared(&sAlo[0][0]) + offA;

    load_g(0);
    for (int kb = 0; kb < din; kb += 16) {
        store_smem();
        __syncthreads();
        if (kb + 16 < din) load_g(kb + 16);

        unsigned bh[4][2], bl[4][2];
        #pragma unroll
        for (int in = 0; in < 4; in++) {
            int bc = wn + gid + in * 8;
            bh[in][0] = sBhi[tg][bc];
            bh[in][1] = sBhi[tg + 4][bc];
            bl[in][0] = sBlo[tg][bc];
            bl[in][1] = sBlo[tg + 4][bc];
        }
        #pragma unroll
        for (int im = 0; im < 4; im++) {
            unsigned ah[4], al[4];
            ldsm4(ah, addrAhi + im * 768);
            ldsm4(al, addrAlo + im * 768);
            #pragma unroll
            for (int in = 0; in < 4; in++) {
                mma_bf16(d[im][in], ah, bh[in]);
                mma_bf16(d[im][in], ah, bl[in]);
                mma_bf16(d[im][in], al, bh[in]);
            }
        }
        __syncthreads();
    }

    // --- epilogue: route by region (q|k -> bf16 caches, v|s -> fp32 vs)
    #pragma unroll
    for (int im = 0; im < 4; im++) {
        int row0 = m0 + wm + im * 16 + gid;
        #pragma unroll
        for (int in = 0; in < 4; in++) {
            int col = n0 + wn + in * 8 + tg * 2;
            float b0 = __ldg(&bias[col]);
            float b1 = __ldg(&bias[col + 1]);
            int reg = col / HC;           // HC even, col even -> pair same region
            int c   = col - reg * HC;
            #pragma unroll
            for (int half = 0; half < 2; half++) {
                int row = row0 + half * 8;
                if (row >= N) continue;
                float2 o = half ? make_float2(d[im][in].z + b0, d[im][in].w + b1)
                                : make_float2(d[im][in].x + b0, d[im][in].y + b1);
                if (reg == 0)
                    *(__nv_bfloat162*)&qb[(size_t)row * HC + c] = __float22bfloat162_rn(o);
                else if (reg == 1)
                    *(__nv_bfloat162*)&kbuf[(size_t)row * HC + c] = __float22bfloat162_rn(o);
                else if (reg == 2)
                    *(float2*)&vs[(size_t)row * 2 * HC + c] = o;
                else
                    *(float2*)&vs[(size_t)row * 2 * HC + HC + c] = o;
            }
        }
    }
}

// =====================================================================
// CSR build
// =====================================================================
__global__ void zero_cnt_kernel(int* __restrict__ cnt, int n)
{
    int i = blockIdx.x * blockDim.x + threadIdx.x;
    if (i < n) cnt[i] = 0;
}

__global__ void hist_kernel(const int* __restrict__ dst, int* __restrict__ cnt, int E)
{
    int e = blockIdx.x * blockDim.x + threadIdx.x;
    if (e < E) atomicAdd(&cnt[dst[e]], 1);
}

__global__ void scan_block_kernel(const int* __restrict__ cnt,
                                  int* __restrict__ row,
                                  int* __restrict__ bsum, int n)
{
    __shared__ int sh[512];
    int t = threadIdx.x;
    int g = blockIdx.x * 512 + t;
    int v = (g < n) ? cnt[g] : 0;
    sh[t] = v;
    __syncthreads();
    #pragma unroll
    for (int off = 1; off < 512; off <<= 1) {
        int tmp = (t >= off) ? sh[t - off] : 0;
        __syncthreads();
        sh[t] += tmp;
        __syncthreads();
    }
    if (g < n) row[g] = sh[t] - v;
    if (t == 511) bsum[blockIdx.x] = sh[511];
}

__global__ void scan_bsum_kernel(const int* __restrict__ bsum,
                                 int* __restrict__ boff, int nb)
{
    __shared__ int sh[256];
    int t = threadIdx.x;
    int v = (t < nb) ? bsum[t] : 0;
    sh[t] = v;
    __syncthreads();
    #pragma unroll
    for (int off = 1; off < 256; off <<= 1) {
        int tmp = (t >= off) ? sh[t - off] : 0;
        __syncthreads();
        sh[t] += tmp;
        __syncthreads();
    }
    boff[t] = sh[t] - v;
}

__global__ void scan_add_kernel(int* __restrict__ row, const int* __restrict__ boff,
                                int* __restrict__ cur, int n)
{
    int g = blockIdx.x * blockDim.x + threadIdx.x;
    if (g < n) {
        int r = row[g] + boff[g >> 9];
        row[g] = r;
        cur[g] = r;
    }
}

__global__ void scatter_kernel(const int* __restrict__ src, const int* __restrict__ dst,
                               int* __restrict__ cur, int* __restrict__ csrc, int E)
{
    int e = blockIdx.x * blockDim.x + threadIdx.x;
    if (e < E) {
        int p = atomicAdd(&cur[dst[e]], 1);
        csrc[p] = src[e];
    }
}

// =====================================================================
// Attention: q,k bf16 caches, v fp32 (vs region 0), skip fp32 (region 1).
// One warp per (dst,head); LPE lanes/edge, 32/LPE edges in flight.
// No online max (logits O(1); softmax shift-invariant).
// =====================================================================
template <int LPE>
__global__ void attn_kernel(const __nv_bfloat16* __restrict__ qb,
                            const __nv_bfloat16* __restrict__ kb,
                            const float* __restrict__ vs,
                            const int* __restrict__ row,
                            const int* __restrict__ cnt,
                            const int* __restrict__ csrc,
                            float* __restrict__ dstb,
                            int H, float scale, int relu, int NHtot)
{
    constexpr int EPW = 32 / LPE;
    constexpr int C   = LPE * 4;

    int w    = (blockIdx.x * blockDim.x + threadIdx.x) >> 5;
    int lane = threadIdx.x & 31;
    if (w >= NHtot) return;
    int n = w / H;
    int h = w - n * H;
    const int HC = H * C;
    int sl  = lane & (LPE - 1);
    int sub = lane / LPE;

    // q (bf16 -> fp32 once)
    uint2 qraw = *(const uint2*)&qb[(size_t)n * HC + h * C + sl * 4];
    float2 q01 = bf2f(qraw.x);
    float2 q23 = bf2f(qraw.y);

    int start = row[n];
    int deg   = cnt[n];

    float  l = 0.f;
    float4 acc = make_float4(0.f, 0.f, 0.f, 0.f);

    for (int base = 0; base < deg; base += 32) {
        int nb = min(32, deg - base);
        int sp = (lane < nb) ? __ldg(&csrc[start + base + lane]) : 0;
        for (int g = 0; g * EPW < nb; g++) {
            int  slot  = g * EPW + sub;
            bool valid = slot < nb;
            int  s     = __shfl_sync(0xffffffffu, sp, slot & 31);
            uint2 kraw = __ldg((const uint2*)&kb[(size_t)s * HC + h * C + sl * 4]);
            float2 f01 = bf2f(kraw.x);
            float2 f23 = bf2f(kraw.y);
            float4 v4  = __ldg((const float4*)&vs[(size_t)s * 2 * HC + h * C + sl * 4]);

            float dot = q01.x * f01.x;
            dot = fmaf(q01.y, f01.y, dot);
            dot = fmaf(q23.x, f23.x, dot);
            dot = fmaf(q23.y, f23.y, dot);
            #pragma unroll
            for (int o = 1; o < LPE; o <<= 1)
                dot += __shfl_xor_sync(0xffffffffu, dot, o);

            float p = valid ? __expf(dot * scale) : 0.f;
            l += p;
            acc.x = fmaf(p, v4.x, acc.x);
            acc.y = fmaf(p, v4.y, acc.y);
            acc.z = fmaf(p, v4.z, acc.z);
            acc.w = fmaf(p, v4.w, acc.w);
        }
    }

    #pragma unroll
    for (int o = LPE; o < 32; o <<= 1) {
        l     += __shfl_xor_sync(0xffffffffu, l, o);
        acc.x += __shfl_xor_sync(0xffffffffu, acc.x, o);
        acc.y += __shfl_xor_sync(0xffffffffu, acc.y, o);
        acc.z += __shfl_xor_sync(0xffffffffu, acc.z, o);
        acc.w += __shfl_xor_sync(0xffffffffu, acc.w, o);
    }

    float inv = 1.0f / (l + 1e-16f);
    if (lane < LPE) {
        float4 o4 = *(const float4*)&vs[(size_t)n * 2 * HC + HC + h * C + lane * 4]; // skip
        o4.x += acc.x * inv;
        o4.y += acc.y * inv;
        o4.z += acc.z * inv;
        o4.w += acc.w * inv;
        if (relu) {
            o4.x = fmaxf(o4.x, 0.f);
            o4.y = fmaxf(o4.y, 0.f);
            o4.z = fmaxf(o4.z, 0.f);
            o4.w = fmaxf(o4.w, 0.f);
        }
        *(float4*)&dstb[(size_t)n * HC + h * C + lane * 4] = o4;
    }
}

// =====================================================================
// Host-side orchestration
// =====================================================================
static void* sym_addr(const void* symbol)
{
    void* p = nullptr;
    cudaGetSymbolAddress(&p, symbol);
    return p;
}

static void launch_attn(const __nv_bfloat16* qb, const __nv_bfloat16* kb,
                        const float* vs, const int* row, const int* cnt,
                        const int* csrc, float* dstb, int N, int H, int C, bool relu)
{
    int NH = N * H;
    int blocks = (NH * 32 + 255) / 256;
    float scale = 1.0f / sqrtf((float)C);
    if (C == 32)
        attn_kernel<8><<<blocks, 256>>>(qb, kb, vs, row, cnt, csrc, dstb, H, scale, relu ? 1 : 0, NH);
    else
        attn_kernel<16><<<blocks, 256>>>(qb, kb, vs, row, cnt, csrc, dstb, H, scale, relu ? 1 : 0, NH);
}

extern "C" void kernel_launch(void* const* d_in, const int* in_sizes, int n_in,
                              void* d_out, int out_size)
{
    const float* x  = (const float*)d_in[0];
    const int*   ei = (const int*)d_in[1];
    const int N = in_sizes[0] / 64;
    const int E = in_sizes[1] / 2;
    const int* src = ei;
    const int* dst = ei + E;

    const float* W[24];
    for (int i = 0; i < 24; i++) W[i] = (const float*)d_in[2 + i];

    __nv_bfloat16* qb = (__nv_bfloat16*)sym_addr(g_qb);
    __nv_bfloat16* kb = (__nv_bfloat16*)sym_addr(g_kb);
    float* vs   = (float*)sym_addr(g_vs);
    float* h1   = (float*)sym_addr(g_h1);
    float* h2   = (float*)sym_addr(g_h2);
    float* wp   = (float*)sym_addr(g_wp);
    float* bp   = (float*)sym_addr(g_bp);
    int*   cnt  = (int*)sym_addr(g_cnt);
    int*   row  = (int*)sym_addr(g_row);
    int*   cur  = (int*)sym_addr(g_cur);
    int*   bsum = (int*)sym_addr(g_bsum);
    int*   boff = (int*)sym_addr(g_boff);
    int*   csrc = (int*)sym_addr(g_csrc);
    float* out  = (float*)d_out;

    float* wp1 = wp;            float* bp1 = bp;
    float* wp2 = wp + 57344;    float* bp2 = bp + 896;
    float* wp3 = wp + 172032;   float* bp3 = bp + 1408;

    int nscan = (N + 511) / 512;

    // launch order keeps layer-1 GEMM in the ncu capture slot (#4)
    pack_w<<<(64 * 896 + 255) / 256, 256>>>(W[0], W[2], W[4], W[6], W[1], W[3], W[5], W[7],
                                            wp1, bp1, 64, 224);
    zero_cnt_kernel<<<(N + 255) / 256, 256>>>(cnt, N);
    hist_kernel<<<(E + 255) / 256, 256>>>(dst, cnt, E);

    // Layer 1 fused GEMM: [N,64] x [64,896]
    {
        dim3 grid((N + 127) / 128, 896 / 128);
        gemm_bf16s<<<grid, 256>>>(x, wp1, bp1, qb, kb, vs, N, 64, 896);
    }

    scan_block_kernel<<<nscan, 512>>>(cnt, row, bsum, N);
    scan_bsum_kernel<<<1, 256>>>(bsum, boff, nscan);
    scan_add_kernel<<<(N + 255) / 256, 256>>>(row, boff, cur, N);
    scatter_kernel<<<(E + 255) / 256, 256>>>(src, dst, cur, csrc, E);
    pack_w<<<(224 * 512 + 255) / 256, 256>>>(W[8], W[10], W[12], W[14], W[9], W[11], W[13], W[15],
                                             wp2, bp2, 224, 128);
    pack_w<<<(128 * 256 + 255) / 256, 256>>>(W[16], W[18], W[20], W[22], W[17], W[19], W[21], W[23],
                                             wp3, bp3, 128, 64);

    // Layer 1 attn: H=7, C=32, relu -> h1
    launch_attn(qb, kb, vs, row, cnt, csrc, h1, N, 7, 32, true);

    // Layer 2: [N,224] x [224,512]
    {
        dim3 grid((N + 127) / 128, 512 / 128);
        gemm_bf16s<<<grid, 256>>>(h1, wp2, bp2, qb, kb, vs, N, 224, 512);
    }
    launch_attn(qb, kb, vs, row, cnt, csrc, h2, N, 4, 32, true);

    // Layer 3: [N,128] x [128,256]
    {
        dim3 grid((N + 127) / 128, 256 / 128);
        gemm_bf16s<<<grid, 256>>>(h2, wp3, bp3, qb, kb, vs, N, 128, 64 * 4);
    }
    launch_attn(qb, kb, vs, row, cnt, csrc, out, N, 1, 64, false);
}

// round 10
// speedup vs baseline: 1.0969x; 1.0969x over previous
#include <cuda_runtime.h>
#include <cuda_bf16.h>
#include <math.h>

#define NN 100000
#define EE 800000

// ---------------- scratch (device globals; no allocations) ----------------
__device__ float g_qkvs[NN * 896];          // fused q|k|v|skip, stride 4*HC
__device__ float g_h1[NN * 224];
__device__ float g_h2[NN * 128];
__device__ float g_wp[204800];              // packed weights, 3 layers
__device__ float g_bp[1664];                // packed biases
// CSR scratch
__device__ int g_cnt[NN];
__device__ int g_row[NN + 1];
__device__ int g_cur[NN];
__device__ int g_bsum[256];
__device__ int g_boff[256];
__device__ int g_csrc[EE];

// ---------------- helpers ---------------------------------------------------
__device__ __forceinline__ void split_pack(float a, float b, unsigned& hi, unsigned& lo)
{
    __nv_bfloat16 ha = __float2bfloat16(a);
    __nv_bfloat16 hb = __float2bfloat16(b);
    __nv_bfloat16 la = __float2bfloat16(a - __bfloat162float(ha));
    __nv_bfloat16 lb = __float2bfloat16(b - __bfloat162float(hb));
    __nv_bfloat162 h2 = __halves2bfloat162(ha, hb);
    __nv_bfloat162 l2 = __halves2bfloat162(la, lb);
    hi = *(unsigned*)&h2;
    lo = *(unsigned*)&l2;
}

__device__ __forceinline__ void mma_bf16(float4& d, const unsigned a[4], const unsigned b[2])
{
    asm volatile("mma.sync.aligned.m16n8k16.row.col.f32.bf16.bf16.f32 "
                 "{%0,%1,%2,%3}, {%4,%5,%6,%7}, {%8,%9}, {%0,%1,%2,%3};"
                 : "+f"(d.x), "+f"(d.y), "+f"(d.z), "+f"(d.w)
                 : "r"(a[0]), "r"(a[1]), "r"(a[2]), "r"(a[3]),
                   "r"(b[0]), "r"(b[1]));
}

__device__ __forceinline__ void ldsm4(unsigned a[4], unsigned addr)
{
    asm volatile("ldmatrix.sync.aligned.m8n8.x4.shared.b16 {%0,%1,%2,%3}, [%4];"
                 : "=r"(a[0]), "=r"(a[1]), "=r"(a[2]), "=r"(a[3]) : "r"(addr));
}

// =====================================================================
// Weight pack: Wp[kk][j*HC + c] = Wj[kk][c]; bp[j*HC + c] = bj[c]
// =====================================================================
__global__ void pack_w(const float* __restrict__ Wq, const float* __restrict__ Wk,
                       const float* __restrict__ Wv, const float* __restrict__ Ws,
                       const float* __restrict__ bq, const float* __restrict__ bk,
                       const float* __restrict__ bv, const float* __restrict__ bs,
                       float* __restrict__ Wp, float* __restrict__ bp,
                       int din, int HC)
{
    int i = blockIdx.x * blockDim.x + threadIdx.x;
    int tot = din * 4 * HC;
    if (i < tot) {
        int kk  = i / (4 * HC);
        int rem = i - kk * 4 * HC;
        int j   = rem / HC;
        int c   = rem - j * HC;
        const float* Wj = (j == 0) ? Wq : (j == 1) ? Wk : (j == 2) ? Wv : Ws;
        Wp[i] = Wj[kk * HC + c];
    }
    if (i < 4 * HC) {
        int j = i / HC, c = i - j * HC;
        const float* bj = (j == 0) ? bq : (j == 1) ? bk : (j == 2) ? bv : bs;
        bp[i] = bj[c];
    }
}

// =====================================================================
// GEMM: Y[N,dout] = X[N,DIN] @ Wp[DIN,dout] + bp
// bf16 3-term split, BM=128, BN=128, BK=16, 8 warps, warp tile 64x32,
// A fragments via ldmatrix.x4. dout multiple of 128; DIN compile-time.
// =====================================================================
template <int DIN>
__global__ void __launch_bounds__(256, 2)
gemm_bf16s(const float* __restrict__ X, const float* __restrict__ W,
           const float* __restrict__ bias, float* __restrict__ Y,
           int N, int dout)
{
    constexpr int BN   = 128;
    constexpr int BSTR = BN + 8;

    __shared__ unsigned sAhi[128][12];
    __shared__ unsigned sAlo[128][12];
    __shared__ unsigned sBhi[8][BSTR];
    __shared__ unsigned sBlo[8][BSTR];

    const int tid  = threadIdx.x;
    const int lane = tid & 31;
    const int warp = tid >> 5;
    const int wm   = (warp & 1) * 64;
    const int wn   = (warp >> 1) * 32;
    const int m0   = blockIdx.x * 128;
    const int n0   = blockIdx.y * BN;

    const int xr  = tid >> 1;
    const int xk  = (tid & 1) * 8;
    const int bpr = tid >> 5;            // B k-pair row 0..7
    const int bn0 = (tid & 31) * 4;

    float4 xreg0, xreg1, wreg0, wreg1;

    auto load_g = [&](int kb_) {
        int row = m0 + xr;
        if (row < N) {
            xreg0 = *(const float4*)&X[(size_t)row * DIN + kb_ + xk];
            xreg1 = *(const float4*)&X[(size_t)row * DIN + kb_ + xk + 4];
        } else {
            xreg0 = make_float4(0.f, 0.f, 0.f, 0.f);
            xreg1 = xreg0;
        }
        int col = n0 + bn0;
        wreg0 = *(const float4*)&W[(size_t)(kb_ + 2 * bpr) * dout + col];
        wreg1 = *(const float4*)&W[(size_t)(kb_ + 2 * bpr + 1) * dout + col];
    };

    auto store_smem = [&]() {
        uint4 hi4, lo4;
        split_pack(xreg0.x, xreg0.y, hi4.x, lo4.x);
        split_pack(xreg0.z, xreg0.w, hi4.y, lo4.y);
        split_pack(xreg1.x, xreg1.y, hi4.z, lo4.z);
        split_pack(xreg1.z, xreg1.w, hi4.w, lo4.w);
        *(uint4*)&sAhi[xr][xk >> 1] = hi4;
        *(uint4*)&sAlo[xr][xk >> 1] = lo4;
        split_pack(wreg0.x, wreg1.x, hi4.x, lo4.x);
        split_pack(wreg0.y, wreg1.y, hi4.y, lo4.y);
        split_pack(wreg0.z, wreg1.z, hi4.z, lo4.z);
        split_pack(wreg0.w, wreg1.w, hi4.w, lo4.w);
        *(uint4*)&sBhi[bpr][bn0] = hi4;
        *(uint4*)&sBlo[bpr][bn0] = lo4;
    };

    float4 d[4][4];
    #pragma unroll
    for (int i = 0; i < 4; i++)
        #pragma unroll
        for (int j = 0; j < 4; j++) d[i][j] = make_float4(0.f, 0.f, 0.f, 0.f);

    const int tg  = lane & 3;
    const int gid = lane >> 2;

    const int arow = (lane & 7) + ((lane >> 3) & 1) * 8;
    const int akp  = (lane >> 4) * 4;
    const unsigned offA = ((wm + arow) * 12 + akp) * 4;
    const unsigned addrAhi = (unsigned)__cvta_generic_to_shared(&sAhi[0][0]) + offA;
    const unsigned addrAlo = (unsigned)__cvta_generic_to_shared(&sAlo[0][0]) + offA;

    load_g(0);
    #pragma unroll 1
    for (int kb = 0; kb < DIN; kb += 16) {
        store_smem();
        __syncthreads();
        if (kb + 16 < DIN) load_g(kb + 16);

        unsigned bh[4][2], bl[4][2];
        #pragma unroll
        for (int in = 0; in < 4; in++) {
            int bc = wn + gid + in * 8;
            bh[in][0] = sBhi[tg][bc];
            bh[in][1] = sBhi[tg + 4][bc];
            bl[in][0] = sBlo[tg][bc];
            bl[in][1] = sBlo[tg + 4][bc];
        }
        #pragma unroll
        for (int im = 0; im < 4; im++) {
            unsigned ah[4], al[4];
            ldsm4(ah, addrAhi + im * 768);
            ldsm4(al, addrAlo + im * 768);
            #pragma unroll
            for (int in = 0; in < 4; in++) {
                mma_bf16(d[im][in], ah, bh[in]);
                mma_bf16(d[im][in], ah, bl[in]);
                mma_bf16(d[im][in], al, bh[in]);
            }
        }
        __syncthreads();
    }

    // --- epilogue: plain fp32 writes (full-sector float2 stores)
    #pragma unroll
    for (int im = 0; im < 4; im++) {
        int row = m0 + wm + im * 16 + gid;
        #pragma unroll
        for (int in = 0; in < 4; in++) {
            int col = n0 + wn + in * 8 + tg * 2;
            float b0 = __ldg(&bias[col]);
            float b1 = __ldg(&bias[col + 1]);
            if (row < N)
                *(float2*)&Y[(size_t)row * dout + col] =
                    make_float2(d[im][in].x + b0, d[im][in].y + b1);
            if (row + 8 < N)
                *(float2*)&Y[(size_t)(row + 8) * dout + col] =
                    make_float2(d[im][in].z + b0, d[im][in].w + b1);
        }
    }
}

// =====================================================================
// CSR build
// =====================================================================
__global__ void zero_cnt_kernel(int* __restrict__ cnt, int n)
{
    int i = blockIdx.x * blockDim.x + threadIdx.x;
    if (i < n) cnt[i] = 0;
}

__global__ void hist_kernel(const int* __restrict__ dst, int* __restrict__ cnt, int E)
{
    int e = blockIdx.x * blockDim.x + threadIdx.x;
    if (e < E) atomicAdd(&cnt[dst[e]], 1);
}

__global__ void scan_block_kernel(const int* __restrict__ cnt,
                                  int* __restrict__ row,
                                  int* __restrict__ bsum, int n)
{
    __shared__ int sh[512];
    int t = threadIdx.x;
    int g = blockIdx.x * 512 + t;
    int v = (g < n) ? cnt[g] : 0;
    sh[t] = v;
    __syncthreads();
    #pragma unroll
    for (int off = 1; off < 512; off <<= 1) {
        int tmp = (t >= off) ? sh[t - off] : 0;
        __syncthreads();
        sh[t] += tmp;
        __syncthreads();
    }
    if (g < n) row[g] = sh[t] - v;
    if (t == 511) bsum[blockIdx.x] = sh[511];
}

__global__ void scan_bsum_kernel(const int* __restrict__ bsum,
                                 int* __restrict__ boff, int nb)
{
    __shared__ int sh[256];
    int t = threadIdx.x;
    int v = (t < nb) ? bsum[t] : 0;
    sh[t] = v;
    __syncthreads();
    #pragma unroll
    for (int off = 1; off < 256; off <<= 1) {
        int tmp = (t >= off) ? sh[t - off] : 0;
        __syncthreads();
        sh[t] += tmp;
        __syncthreads();
    }
    boff[t] = sh[t] - v;
}

__global__ void scan_add_kernel(int* __restrict__ row, const int* __restrict__ boff,
                                int* __restrict__ cur, int n)
{
    int g = blockIdx.x * blockDim.x + threadIdx.x;
    if (g < n) {
        int r = row[g] + boff[g >> 9];
        row[g] = r;
        cur[g] = r;
    }
}

__global__ void scatter_kernel(const int* __restrict__ src, const int* __restrict__ dst,
                               int* __restrict__ cur, int* __restrict__ csrc, int E)
{
    int e = blockIdx.x * blockDim.x + threadIdx.x;
    if (e < E) {
        int p = atomicAdd(&cur[dst[e]], 1);
        csrc[p] = src[e];
    }
}

// =====================================================================
// Attention over fused qkvs buffer (stride 4*HC, regions q|k|v|s).
// One warp per (dst,head); LPE lanes/edge, 32/LPE edges in flight.
// No online max (logits O(1) by construction; softmax shift-invariant).
// =====================================================================
template <int LPE>
__global__ void attn_kernel(const float* __restrict__ qkvs,
                            const int* __restrict__ row,
                            const int* __restrict__ cnt,
                            const int* __restrict__ csrc,
                            float* __restrict__ dstb,
                            int H, float scale, int relu, int NHtot)
{
    constexpr int EPW = 32 / LPE;
    constexpr int C   = LPE * 4;

    int w    = (blockIdx.x * blockDim.x + threadIdx.x) >> 5;
    int lane = threadIdx.x & 31;
    if (w >= NHtot) return;
    int n = w / H;
    int h = w - n * H;
    const int HC = H * C;
    const int S  = 4 * HC;
    int sl  = lane & (LPE - 1);
    int sub = lane / LPE;

    float4 q4 = *(const float4*)&qkvs[n * S + h * C + sl * 4];

    int start = row[n];
    int deg   = cnt[n];

    float  l = 0.f;
    float4 acc = make_float4(0.f, 0.f, 0.f, 0.f);

    for (int base = 0; base < deg; base += 32) {
        int nb = min(32, deg - base);
        int sp = (lane < nb) ? __ldg(&csrc[start + base + lane]) : 0;
        for (int g = 0; g * EPW < nb; g++) {
            int  slot  = g * EPW + sub;
            bool valid = slot < nb;
            int  s     = __shfl_sync(0xffffffffu, sp, slot & 31);
            int  off   = s * S + HC + h * C + sl * 4;
            float4 k4 = __ldg((const float4*)&qkvs[off]);
            float4 v4 = __ldg((const float4*)&qkvs[off + HC]);

            float dot = q4.x * k4.x;
            dot = fmaf(q4.y, k4.y, dot);
            dot = fmaf(q4.z, k4.z, dot);
            dot = fmaf(q4.w, k4.w, dot);
            #pragma unroll
            for (int o = 1; o < LPE; o <<= 1)
                dot += __shfl_xor_sync(0xffffffffu, dot, o);

            float p = valid ? __expf(dot * scale) : 0.f;
            l += p;
            acc.x = fmaf(p, v4.x, acc.x);
            acc.y = fmaf(p, v4.y, acc.y);
            acc.z = fmaf(p, v4.z, acc.z);
            acc.w = fmaf(p, v4.w, acc.w);
        }
    }

    #pragma unroll
    for (int o = LPE; o < 32; o <<= 1) {
        l     += __shfl_xor_sync(0xffffffffu, l, o);
        acc.x += __shfl_xor_sync(0xffffffffu, acc.x, o);
        acc.y += __shfl_xor_sync(0xffffffffu, acc.y, o);
        acc.z += __shfl_xor_sync(0xffffffffu, acc.z, o);
        acc.w += __shfl_xor_sync(0xffffffffu, acc.w, o);
    }

    float inv = 1.0f / (l + 1e-16f);
    if (lane < LPE) {
        float4 o4 = *(const float4*)&qkvs[n * S + 3 * HC + h * C + lane * 4];  // skip
        o4.x += acc.x * inv;
        o4.y += acc.y * inv;
        o4.z += acc.z * inv;
        o4.w += acc.w * inv;
        if (relu) {
            o4.x = fmaxf(o4.x, 0.f);
            o4.y = fmaxf(o4.y, 0.f);
            o4.z = fmaxf(o4.z, 0.f);
            o4.w = fmaxf(o4.w, 0.f);
        }
        *(float4*)&dstb[n * HC + h * C + lane * 4] = o4;
    }
}

// =====================================================================
// Host-side orchestration
// =====================================================================
static void* sym_addr(const void* symbol)
{
    void* p = nullptr;
    cudaGetSymbolAddress(&p, symbol);
    return p;
}

static void launch_attn(const float* qkvs, const int* row, const int* cnt,
                        const int* csrc, float* dstb, int N, int H, int C, bool relu)
{
    int NH = N * H;
    int blocks = (NH * 32 + 255) / 256;
    float scale = 1.0f / sqrtf((float)C);
    if (C == 32)
        attn_kernel<8><<<blocks, 256>>>(qkvs, row, cnt, csrc, dstb, H, scale, relu ? 1 : 0, NH);
    else
        attn_kernel<16><<<blocks, 256>>>(qkvs, row, cnt, csrc, dstb, H, scale, relu ? 1 : 0, NH);
}

extern "C" void kernel_launch(void* const* d_in, const int* in_sizes, int n_in,
                              void* d_out, int out_size)
{
    const float* x  = (const float*)d_in[0];
    const int*   ei = (const int*)d_in[1];
    const int N = in_sizes[0] / 64;
    const int E = in_sizes[1] / 2;
    const int* src = ei;
    const int* dst = ei + E;

    const float* W[24];
    for (int i = 0; i < 24; i++) W[i] = (const float*)d_in[2 + i];

    float* qkvs = (float*)sym_addr(g_qkvs);
    float* h1   = (float*)sym_addr(g_h1);
    float* h2   = (float*)sym_addr(g_h2);
    float* wp   = (float*)sym_addr(g_wp);
    float* bp   = (float*)sym_addr(g_bp);
    int*   cnt  = (int*)sym_addr(g_cnt);
    int*   row  = (int*)sym_addr(g_row);
    int*   cur  = (int*)sym_addr(g_cur);
    int*   bsum = (int*)sym_addr(g_bsum);
    int*   boff = (int*)sym_addr(g_boff);
    int*   csrc = (int*)sym_addr(g_csrc);
    float* out  = (float*)d_out;

    float* wp1 = wp;            float* bp1 = bp;
    float* wp2 = wp + 57344;    float* bp2 = bp + 896;
    float* wp3 = wp + 172032;   float* bp3 = bp + 1408;

    int nscan = (N + 511) / 512;

    // launch order keeps layer-1 GEMM in the ncu capture slot (#4)
    pack_w<<<(64 * 896 + 255) / 256, 256>>>(W[0], W[2], W[4], W[6], W[1], W[3], W[5], W[7],
                                            wp1, bp1, 64, 224);
    zero_cnt_kernel<<<(N + 255) / 256, 256>>>(cnt, N);
    hist_kernel<<<(E + 255) / 256, 256>>>(dst, cnt, E);

    // Layer 1 fused GEMM: [N,64] x [64,896]   (launch #4)
    {
        dim3 grid((N + 127) / 128, 896 / 128);
        gemm_bf16s<64><<<grid, 256>>>(x, wp1, bp1, qkvs, N, 896);
    }

    scan_block_kernel<<<nscan, 512>>>(cnt, row, bsum, N);
    scan_bsum_kernel<<<1, 256>>>(bsum, boff, nscan);
    scan_add_kernel<<<(N + 255) / 256, 256>>>(row, boff, cur, N);
    scatter_kernel<<<(E + 255) / 256, 256>>>(src, dst, cur, csrc, E);
    pack_w<<<(224 * 512 + 255) / 256, 256>>>(W[8], W[10], W[12], W[14], W[9], W[11], W[13], W[15],
                                             wp2, bp2, 224, 128);
    pack_w<<<(128 * 256 + 255) / 256, 256>>>(W[16], W[18], W[20], W[22], W[17], W[19], W[21], W[23],
                                             wp3, bp3, 128, 64);

    // Layer 1 attn: H=7, C=32, relu -> h1
    launch_attn(qkvs, row, cnt, csrc, h1, N, 7, 32, true);

    // Layer 2: [N,224] x [224,512]
    {
        dim3 grid((N + 127) / 128, 512 / 128);
        gemm_bf16s<224><<<grid, 256>>>(h1, wp2, bp2, qkvs, N, 512);
    }
    launch_attn(qkvs, row, cnt, csrc, h2, N, 4, 32, true);

    // Layer 3: [N,128] x [128,256]
    {
        dim3 grid((N + 127) / 128, 256 / 128);
        gemm_bf16s<128><<<grid, 256>>>(h2, wp3, bp3, qkvs, N, 256);
    }
    launch_attn(qkvs, row, cnt, csrc, out, N, 1, 64, false);
}

// round 11
// speedup vs baseline: 1.1607x; 1.0581x over previous
#include <cuda_runtime.h>
#include <cuda_bf16.h>
#include <math.h>

#define NN 100000
#define EE 800000

// ---------------- scratch (device globals; no allocations) ----------------
__device__ float g_qkvs[NN * 896];          // fused q|k|v|skip, stride 4*HC
__device__ float g_h1[NN * 224];
__device__ float g_h2[NN * 128];
__device__ float g_wp[204800];              // packed weights, 3 layers
__device__ float g_bp[1664];                // packed biases
// CSR scratch
__device__ int g_cnt[NN];
__device__ int g_row[NN + 1];
__device__ int g_cur[NN];
__device__ int g_bsum[256];
__device__ int g_boff[256];
__device__ int g_csrc[EE];

// ---------------- helpers ---------------------------------------------------
__device__ __forceinline__ void split_pack(float a, float b, unsigned& hi, unsigned& lo)
{
    __nv_bfloat16 ha = __float2bfloat16(a);
    __nv_bfloat16 hb = __float2bfloat16(b);
    __nv_bfloat16 la = __float2bfloat16(a - __bfloat162float(ha));
    __nv_bfloat16 lb = __float2bfloat16(b - __bfloat162float(hb));
    __nv_bfloat162 h2 = __halves2bfloat162(ha, hb);
    __nv_bfloat162 l2 = __halves2bfloat162(la, lb);
    hi = *(unsigned*)&h2;
    lo = *(unsigned*)&l2;
}

__device__ __forceinline__ void mma_bf16(float4& d, const unsigned a[4], const unsigned b[2])
{
    asm volatile("mma.sync.aligned.m16n8k16.row.col.f32.bf16.bf16.f32 "
                 "{%0,%1,%2,%3}, {%4,%5,%6,%7}, {%8,%9}, {%0,%1,%2,%3};"
                 : "+f"(d.x), "+f"(d.y), "+f"(d.z), "+f"(d.w)
                 : "r"(a[0]), "r"(a[1]), "r"(a[2]), "r"(a[3]),
                   "r"(b[0]), "r"(b[1]));
}

__device__ __forceinline__ void ldsm4(unsigned a[4], unsigned addr)
{
    asm volatile("ldmatrix.sync.aligned.m8n8.x4.shared.b16 {%0,%1,%2,%3}, [%4];"
                 : "=r"(a[0]), "=r"(a[1]), "=r"(a[2]), "=r"(a[3]) : "r"(addr));
}

// =====================================================================
// Weight pack: Wp[kk][j*HC + c] = Wj[kk][c]; bp[j*HC + c] = bj[c]
// =====================================================================
__global__ void pack_w(const float* __restrict__ Wq, const float* __restrict__ Wk,
                       const float* __restrict__ Wv, const float* __restrict__ Ws,
                       const float* __restrict__ bq, const float* __restrict__ bk,
                       const float* __restrict__ bv, const float* __restrict__ bs,
                       float* __restrict__ Wp, float* __restrict__ bp,
                       int din, int HC)
{
    int i = blockIdx.x * blockDim.x + threadIdx.x;
    int tot = din * 4 * HC;
    if (i < tot) {
        int kk  = i / (4 * HC);
        int rem = i - kk * 4 * HC;
        int j   = rem / HC;
        int c   = rem - j * HC;
        const float* Wj = (j == 0) ? Wq : (j == 1) ? Wk : (j == 2) ? Wv : Ws;
        Wp[i] = Wj[kk * HC + c];
    }
    if (i < 4 * HC) {
        int j = i / HC, c = i - j * HC;
        const float* bj = (j == 0) ? bq : (j == 1) ? bk : (j == 2) ? bv : bs;
        bp[i] = bj[c];
    }
}

// =====================================================================
// GEMM: Y[N,dout] = X[N,DIN] @ Wp[DIN,dout] + bp
// bf16 3-term split, BM=128, BN=128, BK=16, 8 warps, warp tile 64x32,
// A fragments via ldmatrix.x4. dout multiple of 128; DIN compile-time.
// =====================================================================
template <int DIN>
__global__ void __launch_bounds__(256, 2)
gemm_bf16s(const float* __restrict__ X, const float* __restrict__ W,
           const float* __restrict__ bias, float* __restrict__ Y,
           int N, int dout)
{
    constexpr int BN   = 128;
    constexpr int BSTR = BN + 8;

    __shared__ unsigned sAhi[128][12];
    __shared__ unsigned sAlo[128][12];
    __shared__ unsigned sBhi[8][BSTR];
    __shared__ unsigned sBlo[8][BSTR];

    const int tid  = threadIdx.x;
    const int lane = tid & 31;
    const int warp = tid >> 5;
    const int wm   = (warp & 1) * 64;
    const int wn   = (warp >> 1) * 32;
    const int m0   = blockIdx.x * 128;
    const int n0   = blockIdx.y * BN;

    const int xr  = tid >> 1;
    const int xk  = (tid & 1) * 8;
    const int bpr = tid >> 5;            // B k-pair row 0..7
    const int bn0 = (tid & 31) * 4;

    float4 xreg0, xreg1, wreg0, wreg1;

    auto load_g = [&](int kb_) {
        int row = m0 + xr;
        if (row < N) {
            xreg0 = *(const float4*)&X[(size_t)row * DIN + kb_ + xk];
            xreg1 = *(const float4*)&X[(size_t)row * DIN + kb_ + xk + 4];
        } else {
            xreg0 = make_float4(0.f, 0.f, 0.f, 0.f);
            xreg1 = xreg0;
        }
        int col = n0 + bn0;
        wreg0 = *(const float4*)&W[(size_t)(kb_ + 2 * bpr) * dout + col];
        wreg1 = *(const float4*)&W[(size_t)(kb_ + 2 * bpr + 1) * dout + col];
    };

    auto store_smem = [&]() {
        uint4 hi4, lo4;
        split_pack(xreg0.x, xreg0.y, hi4.x, lo4.x);
        split_pack(xreg0.z, xreg0.w, hi4.y, lo4.y);
        split_pack(xreg1.x, xreg1.y, hi4.z, lo4.z);
        split_pack(xreg1.z, xreg1.w, hi4.w, lo4.w);
        *(uint4*)&sAhi[xr][xk >> 1] = hi4;
        *(uint4*)&sAlo[xr][xk >> 1] = lo4;
        split_pack(wreg0.x, wreg1.x, hi4.x, lo4.x);
        split_pack(wreg0.y, wreg1.y, hi4.y, lo4.y);
        split_pack(wreg0.z, wreg1.z, hi4.z, lo4.z);
        split_pack(wreg0.w, wreg1.w, hi4.w, lo4.w);
        *(uint4*)&sBhi[bpr][bn0] = hi4;
        *(uint4*)&sBlo[bpr][bn0] = lo4;
    };

    float4 d[4][4];
    #pragma unroll
    for (int i = 0; i < 4; i++)
        #pragma unroll
        for (int j = 0; j < 4; j++) d[i][j] = make_float4(0.f, 0.f, 0.f, 0.f);

    const int tg  = lane & 3;
    const int gid = lane >> 2;

    const int arow = (lane & 7) + ((lane >> 3) & 1) * 8;
    const int akp  = (lane >> 4) * 4;
    const unsigned offA = ((wm + arow) * 12 + akp) * 4;
    const unsigned addrAhi = (unsigned)__cvta_generic_to_shared(&sAhi[0][0]) + offA;
    const unsigned addrAlo = (unsigned)__cvta_generic_to_shared(&sAlo[0][0]) + offA;

    load_g(0);
    #pragma unroll 1
    for (int kb = 0; kb < DIN; kb += 16) {
        store_smem();
        __syncthreads();
        if (kb + 16 < DIN) load_g(kb + 16);

        unsigned bh[4][2], bl[4][2];
        #pragma unroll
        for (int in = 0; in < 4; in++) {
            int bc = wn + gid + in * 8;
            bh[in][0] = sBhi[tg][bc];
            bh[in][1] = sBhi[tg + 4][bc];
            bl[in][0] = sBlo[tg][bc];
            bl[in][1] = sBlo[tg + 4][bc];
        }
        #pragma unroll
        for (int im = 0; im < 4; im++) {
            unsigned ah[4], al[4];
            ldsm4(ah, addrAhi + im * 768);
            ldsm4(al, addrAlo + im * 768);
            #pragma unroll
            for (int in = 0; in < 4; in++) {
                mma_bf16(d[im][in], ah, bh[in]);
                mma_bf16(d[im][in], ah, bl[in]);
                mma_bf16(d[im][in], al, bh[in]);
            }
        }
        __syncthreads();
    }

    // --- epilogue: plain fp32 writes (full-sector float2 stores)
    #pragma unroll
    for (int im = 0; im < 4; im++) {
        int row = m0 + wm + im * 16 + gid;
        #pragma unroll
        for (int in = 0; in < 4; in++) {
            int col = n0 + wn + in * 8 + tg * 2;
            float b0 = __ldg(&bias[col]);
            float b1 = __ldg(&bias[col + 1]);
            if (row < N)
                *(float2*)&Y[(size_t)row * dout + col] =
                    make_float2(d[im][in].x + b0, d[im][in].y + b1);
            if (row + 8 < N)
                *(float2*)&Y[(size_t)(row + 8) * dout + col] =
                    make_float2(d[im][in].z + b0, d[im][in].w + b1);
        }
    }
}

// =====================================================================
// CSR build
// =====================================================================
__global__ void zero_cnt_kernel(int* __restrict__ cnt, int n)
{
    int i = blockIdx.x * blockDim.x + threadIdx.x;
    if (i < n) cnt[i] = 0;
}

__global__ void hist_kernel(const int* __restrict__ dst, int* __restrict__ cnt, int E)
{
    int e = blockIdx.x * blockDim.x + threadIdx.x;
    if (e < E) atomicAdd(&cnt[dst[e]], 1);
}

__global__ void scan_block_kernel(const int* __restrict__ cnt,
                                  int* __restrict__ row,
                                  int* __restrict__ bsum, int n)
{
    __shared__ int sh[512];
    int t = threadIdx.x;
    int g = blockIdx.x * 512 + t;
    int v = (g < n) ? cnt[g] : 0;
    sh[t] = v;
    __syncthreads();
    #pragma unroll
    for (int off = 1; off < 512; off <<= 1) {
        int tmp = (t >= off) ? sh[t - off] : 0;
        __syncthreads();
        sh[t] += tmp;
        __syncthreads();
    }
    if (g < n) row[g] = sh[t] - v;
    if (t == 511) bsum[blockIdx.x] = sh[511];
}

__global__ void scan_bsum_kernel(const int* __restrict__ bsum,
                                 int* __restrict__ boff, int nb)
{
    __shared__ int sh[256];
    int t = threadIdx.x;
    int v = (t < nb) ? bsum[t] : 0;
    sh[t] = v;
    __syncthreads();
    #pragma unroll
    for (int off = 1; off < 256; off <<= 1) {
        int tmp = (t >= off) ? sh[t - off] : 0;
        __syncthreads();
        sh[t] += tmp;
        __syncthreads();
    }
    boff[t] = sh[t] - v;
}

__global__ void scan_add_kernel(int* __restrict__ row, const int* __restrict__ boff,
                                int* __restrict__ cur, int n)
{
    int g = blockIdx.x * blockDim.x + threadIdx.x;
    if (g < n) {
        int r = row[g] + boff[g >> 9];
        row[g] = r;
        cur[g] = r;
    }
}

__global__ void scatter_kernel(const int* __restrict__ src, const int* __restrict__ dst,
                               int* __restrict__ cur, int* __restrict__ csrc, int E)
{
    int e = blockIdx.x * blockDim.x + threadIdx.x;
    if (e < E) {
        int p = atomicAdd(&cur[dst[e]], 1);
        csrc[p] = src[e];
    }
}

// =====================================================================
// Attention over fused qkvs buffer (stride 4*HC, regions q|k|v|s).
// h-MAJOR warp mapping: warp w -> (h = w/N, n = w%N). The concurrent
// warp window then gathers k/v from ONE head slice (~25.6MB) which is
// L2-resident, instead of thrashing the full multi-head region.
// LPE lanes/edge, 32/LPE edges in flight. No online max (logits O(1)).
// =====================================================================
template <int LPE>
__global__ void attn_kernel(const float* __restrict__ qkvs,
                            const int* __restrict__ row,
                            const int* __restrict__ cnt,
                            const int* __restrict__ csrc,
                            float* __restrict__ dstb,
                            int H, float scale, int relu, int Nn)
{
    constexpr int EPW = 32 / LPE;
    constexpr int C   = LPE * 4;

    int w    = (blockIdx.x * blockDim.x + threadIdx.x) >> 5;
    int lane = threadIdx.x & 31;
    if (w >= Nn * H) return;
    int h = w / Nn;            // h-major: full node sweep per head
    int n = w - h * Nn;
    const int HC = H * C;
    const int S  = 4 * HC;
    int sl  = lane & (LPE - 1);
    int sub = lane / LPE;

    float4 q4 = *(const float4*)&qkvs[n * S + h * C + sl * 4];

    int start = row[n];
    int deg   = cnt[n];

    float  l = 0.f;
    float4 acc = make_float4(0.f, 0.f, 0.f, 0.f);

    for (int base = 0; base < deg; base += 32) {
        int nb = min(32, deg - base);
        int sp = (lane < nb) ? __ldg(&csrc[start + base + lane]) : 0;
        for (int g = 0; g * EPW < nb; g++) {
            int  slot  = g * EPW + sub;
            bool valid = slot < nb;
            int  s     = __shfl_sync(0xffffffffu, sp, slot & 31);
            int  off   = s * S + HC + h * C + sl * 4;
            float4 k4 = __ldg((const float4*)&qkvs[off]);
            float4 v4 = __ldg((const float4*)&qkvs[off + HC]);

            float dot = q4.x * k4.x;
            dot = fmaf(q4.y, k4.y, dot);
            dot = fmaf(q4.z, k4.z, dot);
            dot = fmaf(q4.w, k4.w, dot);
            #pragma unroll
            for (int o = 1; o < LPE; o <<= 1)
                dot += __shfl_xor_sync(0xffffffffu, dot, o);

            float p = valid ? __expf(dot * scale) : 0.f;
            l += p;
            acc.x = fmaf(p, v4.x, acc.x);
            acc.y = fmaf(p, v4.y, acc.y);
            acc.z = fmaf(p, v4.z, acc.z);
            acc.w = fmaf(p, v4.w, acc.w);
        }
    }

    #pragma unroll
    for (int o = LPE; o < 32; o <<= 1) {
        l     += __shfl_xor_sync(0xffffffffu, l, o);
        acc.x += __shfl_xor_sync(0xffffffffu, acc.x, o);
        acc.y += __shfl_xor_sync(0xffffffffu, acc.y, o);
        acc.z += __shfl_xor_sync(0xffffffffu, acc.z, o);
        acc.w += __shfl_xor_sync(0xffffffffu, acc.w, o);
    }

    float inv = 1.0f / (l + 1e-16f);
    if (lane < LPE) {
        float4 o4 = *(const float4*)&qkvs[n * S + 3 * HC + h * C + lane * 4];  // skip
        o4.x += acc.x * inv;
        o4.y += acc.y * inv;
        o4.z += acc.z * inv;
        o4.w += acc.w * inv;
        if (relu) {
            o4.x = fmaxf(o4.x, 0.f);
            o4.y = fmaxf(o4.y, 0.f);
            o4.z = fmaxf(o4.z, 0.f);
            o4.w = fmaxf(o4.w, 0.f);
        }
        *(float4*)&dstb[n * HC + h * C + lane * 4] = o4;
    }
}

// =====================================================================
// Host-side orchestration
// =====================================================================
static void* sym_addr(const void* symbol)
{
    void* p = nullptr;
    cudaGetSymbolAddress(&p, symbol);
    return p;
}

static void launch_attn(const float* qkvs, const int* row, const int* cnt,
                        const int* csrc, float* dstb, int N, int H, int C, bool relu)
{
    int NH = N * H;
    int blocks = (NH * 32 + 255) / 256;
    float scale = 1.0f / sqrtf((float)C);
    if (C == 32)
        attn_kernel<8><<<blocks, 256>>>(qkvs, row, cnt, csrc, dstb, H, scale, relu ? 1 : 0, N);
    else
        attn_kernel<16><<<blocks, 256>>>(qkvs, row, cnt, csrc, dstb, H, scale, relu ? 1 : 0, N);
}

extern "C" void kernel_launch(void* const* d_in, const int* in_sizes, int n_in,
                              void* d_out, int out_size)
{
    const float* x  = (const float*)d_in[0];
    const int*   ei = (const int*)d_in[1];
    const int N = in_sizes[0] / 64;
    const int E = in_sizes[1] / 2;
    const int* src = ei;
    const int* dst = ei + E;

    const float* W[24];
    for (int i = 0; i < 24; i++) W[i] = (const float*)d_in[2 + i];

    float* qkvs = (float*)sym_addr(g_qkvs);
    float* h1   = (float*)sym_addr(g_h1);
    float* h2   = (float*)sym_addr(g_h2);
    float* wp   = (float*)sym_addr(g_wp);
    float* bp   = (float*)sym_addr(g_bp);
    int*   cnt  = (int*)sym_addr(g_cnt);
    int*   row  = (int*)sym_addr(g_row);
    int*   cur  = (int*)sym_addr(g_cur);
    int*   bsum = (int*)sym_addr(g_bsum);
    int*   boff = (int*)sym_addr(g_boff);
    int*   csrc = (int*)sym_addr(g_csrc);
    float* out  = (float*)d_out;

    float* wp1 = wp;            float* bp1 = bp;
    float* wp2 = wp + 57344;    float* bp2 = bp + 896;
    float* wp3 = wp + 172032;   float* bp3 = bp + 1408;

    int nscan = (N + 511) / 512;

    // launch order keeps layer-1 GEMM in the ncu capture slot (#4)
    pack_w<<<(64 * 896 + 255) / 256, 256>>>(W[0], W[2], W[4], W[6], W[1], W[3], W[5], W[7],
                                            wp1, bp1, 64, 224);
    zero_cnt_kernel<<<(N + 255) / 256, 256>>>(cnt, N);
    hist_kernel<<<(E + 255) / 256, 256>>>(dst, cnt, E);

    // Layer 1 fused GEMM: [N,64] x [64,896]   (launch #4)
    {
        dim3 grid((N + 127) / 128, 896 / 128);
        gemm_bf16s<64><<<grid, 256>>>(x, wp1, bp1, qkvs, N, 896);
    }

    scan_block_kernel<<<nscan, 512>>>(cnt, row, bsum, N);
    scan_bsum_kernel<<<1, 256>>>(bsum, boff, nscan);
    scan_add_kernel<<<(N + 255) / 256, 256>>>(row, boff, cur, N);
    scatter_kernel<<<(E + 255) / 256, 256>>>(src, dst, cur, csrc, E);
    pack_w<<<(224 * 512 + 255) / 256, 256>>>(W[8], W[10], W[12], W[14], W[9], W[11], W[13], W[15],
                                             wp2, bp2, 224, 128);
    pack_w<<<(128 * 256 + 255) / 256, 256>>>(W[16], W[18], W[20], W[22], W[17], W[19], W[21], W[23],
                                             wp3, bp3, 128, 64);

    // Layer 1 attn: H=7, C=32, relu -> h1
    launch_attn(qkvs, row, cnt, csrc, h1, N, 7, 32, true);

    // Layer 2: [N,224] x [224,512]
    {
        dim3 grid((N + 127) / 128, 512 / 128);
        gemm_bf16s<224><<<grid, 256>>>(h1, wp2, bp2, qkvs, N, 512);
    }
    launch_attn(qkvs, row, cnt, csrc, h2, N, 4, 32, true);

    // Layer 3: [N,128] x [128,256]
    {
        dim3 grid((N + 127) / 128, 256 / 128);
        gemm_bf16s<128><<<grid, 256>>>(h2, wp3, bp3, qkvs, N, 256);
    }
    launch_attn(qkvs, row, cnt, csrc, out, N, 1, 64, false);
}

// round 12
// speedup vs baseline: 1.1960x; 1.0304x over previous
#include <cuda_runtime.h>
#include <cuda_bf16.h>
#include <cuda_fp16.h>
#include <math.h>

#define NN 100000
#define EE 800000

// ---------------- scratch (device globals; no allocations) ----------------
__device__ float  g_qs[NN * 448];           // fp32 q|skip  [N, 2*HC]
__device__ __half g_kv[NN * 448];           // fp16 fused kv [N*H, 2*C] chunked
__device__ float  g_h1[NN * 224];
__device__ float  g_h2[NN * 128];
__device__ float  g_wp[204800];             // packed weights, 3 layers
__device__ float  g_bp[1664];               // packed biases
// CSR scratch
__device__ int g_cnt[NN];
__device__ int g_row[NN + 1];
__device__ int g_cur[NN];
__device__ int g_bsum[256];
__device__ int g_boff[256];
__device__ int g_csrc[EE];

// ---------------- helpers ---------------------------------------------------
__device__ __forceinline__ void split_pack(float a, float b, unsigned& hi, unsigned& lo)
{
    __nv_bfloat16 ha = __float2bfloat16(a);
    __nv_bfloat16 hb = __float2bfloat16(b);
    __nv_bfloat16 la = __float2bfloat16(a - __bfloat162float(ha));
    __nv_bfloat16 lb = __float2bfloat16(b - __bfloat162float(hb));
    __nv_bfloat162 h2 = __halves2bfloat162(ha, hb);
    __nv_bfloat162 l2 = __halves2bfloat162(la, lb);
    hi = *(unsigned*)&h2;
    lo = *(unsigned*)&l2;
}

__device__ __forceinline__ void mma_bf16(float4& d, const unsigned a[4], const unsigned b[2])
{
    asm volatile("mma.sync.aligned.m16n8k16.row.col.f32.bf16.bf16.f32 "
                 "{%0,%1,%2,%3}, {%4,%5,%6,%7}, {%8,%9}, {%0,%1,%2,%3};"
                 : "+f"(d.x), "+f"(d.y), "+f"(d.z), "+f"(d.w)
                 : "r"(a[0]), "r"(a[1]), "r"(a[2]), "r"(a[3]),
                   "r"(b[0]), "r"(b[1]));
}

__device__ __forceinline__ void ldsm4(unsigned a[4], unsigned addr)
{
    asm volatile("ldmatrix.sync.aligned.m8n8.x4.shared.b16 {%0,%1,%2,%3}, [%4];"
                 : "=r"(a[0]), "=r"(a[1]), "=r"(a[2]), "=r"(a[3]) : "r"(addr));
}

__device__ __forceinline__ float2 h2f(unsigned u)
{
    return __half22float2(*reinterpret_cast<__half2*>(&u));
}

// =====================================================================
// Weight pack: Wp[kk][j*HC + c] = Wj[kk][c]; bp[j*HC + c] = bj[c]
// =====================================================================
__global__ void pack_w(const float* __restrict__ Wq, const float* __restrict__ Wk,
                       const float* __restrict__ Wv, const float* __restrict__ Ws,
                       const float* __restrict__ bq, const float* __restrict__ bk,
                       const float* __restrict__ bv, const float* __restrict__ bs,
                       float* __restrict__ Wp, float* __restrict__ bp,
                       int din, int HC)
{
    int i = blockIdx.x * blockDim.x + threadIdx.x;
    int tot = din * 4 * HC;
    if (i < tot) {
        int kk  = i / (4 * HC);
        int rem = i - kk * 4 * HC;
        int j   = rem / HC;
        int c   = rem - j * HC;
        const float* Wj = (j == 0) ? Wq : (j == 1) ? Wk : (j == 2) ? Wv : Ws;
        Wp[i] = Wj[kk * HC + c];
    }
    if (i < 4 * HC) {
        int j = i / HC, c = i - j * HC;
        const float* bj = (j == 0) ? bq : (j == 1) ? bk : (j == 2) ? bv : bs;
        bp[i] = bj[c];
    }
}

// =====================================================================
// GEMM: X[N,DIN] @ Wp[DIN, 4*HC] + bp, routed epilogue:
//   region 0 (q)  -> qs[row][0..HC)          fp32
//   region 1 (k)  -> kv chunk slots 0..3     fp16
//   region 2 (v)  -> kv chunk slots 4..7     fp16
//   region 3 (s)  -> qs[row][HC..2HC)        fp32
// kv layout: [(row*H + h)*2C] in 16B chunks {k[4j..4j+3], v[4j..4j+3]}.
// bf16 3-term split, BM=128, BN=128, BK=16, warp tile 64x32, ldmatrix A.
// =====================================================================
template <int DIN, int HC, int C>
__global__ void __launch_bounds__(256, 2)
gemm_bf16s(const float* __restrict__ X, const float* __restrict__ W,
           const float* __restrict__ bias,
           float* __restrict__ qs, __half* __restrict__ kv,
           int N)
{
    constexpr int BN   = 128;
    constexpr int BSTR = BN + 8;
    constexpr int DOUT = 4 * HC;
    constexpr int H    = HC / C;

    __shared__ unsigned sAhi[128][12];
    __shared__ unsigned sAlo[128][12];
    __shared__ unsigned sBhi[8][BSTR];
    __shared__ unsigned sBlo[8][BSTR];

    const int tid  = threadIdx.x;
    const int lane = tid & 31;
    const int warp = tid >> 5;
    const int wm   = (warp & 1) * 64;
    const int wn   = (warp >> 1) * 32;
    const int m0   = blockIdx.x * 128;
    const int n0   = blockIdx.y * BN;

    const int xr  = tid >> 1;
    const int xk  = (tid & 1) * 8;
    const int bpr = tid >> 5;            // B k-pair row 0..7
    const int bn0 = (tid & 31) * 4;

    float4 xreg0, xreg1, wreg0, wreg1;

    auto load_g = [&](int kb_) {
        int row = m0 + xr;
        if (row < N) {
            xreg0 = *(const float4*)&X[(size_t)row * DIN + kb_ + xk];
            xreg1 = *(const float4*)&X[(size_t)row * DIN + kb_ + xk + 4];
        } else {
            xreg0 = make_float4(0.f, 0.f, 0.f, 0.f);
            xreg1 = xreg0;
        }
        int col = n0 + bn0;
        wreg0 = *(const float4*)&W[(size_t)(kb_ + 2 * bpr) * DOUT + col];
        wreg1 = *(const float4*)&W[(size_t)(kb_ + 2 * bpr + 1) * DOUT + col];
    };

    auto store_smem = [&]() {
        uint4 hi4, lo4;
        split_pack(xreg0.x, xreg0.y, hi4.x, lo4.x);
        split_pack(xreg0.z, xreg0.w, hi4.y, lo4.y);
        split_pack(xreg1.x, xreg1.y, hi4.z, lo4.z);
        split_pack(xreg1.z, xreg1.w, hi4.w, lo4.w);
        *(uint4*)&sAhi[xr][xk >> 1] = hi4;
        *(uint4*)&sAlo[xr][xk >> 1] = lo4;
        split_pack(wreg0.x, wreg1.x, hi4.x, lo4.x);
        split_pack(wreg0.y, wreg1.y, hi4.y, lo4.y);
        split_pack(wreg0.z, wreg1.z, hi4.z, lo4.z);
        split_pack(wreg0.w, wreg1.w, hi4.w, lo4.w);
        *(uint4*)&sBhi[bpr][bn0] = hi4;
        *(uint4*)&sBlo[bpr][bn0] = lo4;
    };

    float4 d[4][4];
    #pragma unroll
    for (int i = 0; i < 4; i++)
        #pragma unroll
        for (int j = 0; j < 4; j++) d[i][j] = make_float4(0.f, 0.f, 0.f, 0.f);

    const int tg  = lane & 3;
    const int gid = lane >> 2;

    const int arow = (lane & 7) + ((lane >> 3) & 1) * 8;
    const int akp  = (lane >> 4) * 4;
    const unsigned offA = ((wm + arow) * 12 + akp) * 4;
    const unsigned addrAhi = (unsigned)__cvta_generic_to_shared(&sAhi[0][0]) + offA;
    const unsigned addrAlo = (unsigned)__cvta_generic_to_shared(&sAlo[0][0]) + offA;

    load_g(0);
    #pragma unroll 1
    for (int kb = 0; kb < DIN; kb += 16) {
        store_smem();
        __syncthreads();
        if (kb + 16 < DIN) load_g(kb + 16);

        unsigned bh[4][2], bl[4][2];
        #pragma unroll
        for (int in = 0; in < 4; in++) {
            int bc = wn + gid + in * 8;
            bh[in][0] = sBhi[tg][bc];
            bh[in][1] = sBhi[tg + 4][bc];
            bl[in][0] = sBlo[tg][bc];
            bl[in][1] = sBlo[tg + 4][bc];
        }
        #pragma unroll
        for (int im = 0; im < 4; im++) {
            unsigned ah[4], al[4];
            ldsm4(ah, addrAhi + im * 768);
            ldsm4(al, addrAlo + im * 768);
            #pragma unroll
            for (int in = 0; in < 4; in++) {
                mma_bf16(d[im][in], ah, bh[in]);
                mma_bf16(d[im][in], ah, bl[in]);
                mma_bf16(d[im][in], al, bh[in]);
            }
        }
        __syncthreads();
    }

    // --- routed epilogue (all routing arithmetic compile-time strength-reduced)
    #pragma unroll
    for (int im = 0; im < 4; im++) {
        int row0 = m0 + wm + im * 16 + gid;
        #pragma unroll
        for (int in = 0; in < 4; in++) {
            int col = n0 + wn + in * 8 + tg * 2;
            float b0 = __ldg(&bias[col]);
            float b1 = __ldg(&bias[col + 1]);
            int reg = col / HC;           // col even, HC even -> pair same region
            int c   = col - reg * HC;
            #pragma unroll
            for (int half = 0; half < 2; half++) {
                int row = row0 + half * 8;
                if (row >= N) continue;
                float2 o = half ? make_float2(d[im][in].z + b0, d[im][in].w + b1)
                                : make_float2(d[im][in].x + b0, d[im][in].y + b1);
                if (reg == 0) {
                    *(float2*)&qs[(size_t)row * 2 * HC + c] = o;
                } else if (reg == 3) {
                    *(float2*)&qs[(size_t)row * 2 * HC + HC + c] = o;
                } else {
                    int h  = c / C;
                    int ch = c - h * C;
                    size_t base = ((size_t)row * H + h) * 2 * C
                                + (ch >> 2) * 8 + (ch & 3) + (reg == 2 ? 4 : 0);
                    *(__half2*)&kv[base] = __float22half2_rn(o);
                }
            }
        }
    }
}

// =====================================================================
// CSR build
// =====================================================================
__global__ void zero_cnt_kernel(int* __restrict__ cnt, int n)
{
    int i = blockIdx.x * blockDim.x + threadIdx.x;
    if (i < n) cnt[i] = 0;
}

__global__ void hist_kernel(const int* __restrict__ dst, int* __restrict__ cnt, int E)
{
    int e = blockIdx.x * blockDim.x + threadIdx.x;
    if (e < E) atomicAdd(&cnt[dst[e]], 1);
}

__global__ void scan_block_kernel(const int* __restrict__ cnt,
                                  int* __restrict__ row,
                                  int* __restrict__ bsum, int n)
{
    __shared__ int sh[512];
    int t = threadIdx.x;
    int g = blockIdx.x * 512 + t;
    int v = (g < n) ? cnt[g] : 0;
    sh[t] = v;
    __syncthreads();
    #pragma unroll
    for (int off = 1; off < 512; off <<= 1) {
        int tmp = (t >= off) ? sh[t - off] : 0;
        __syncthreads();
        sh[t] += tmp;
        __syncthreads();
    }
    if (g < n) row[g] = sh[t] - v;
    if (t == 511) bsum[blockIdx.x] = sh[511];
}

__global__ void scan_bsum_kernel(const int* __restrict__ bsum,
                                 int* __restrict__ boff, int nb)
{
    __shared__ int sh[256];
    int t = threadIdx.x;
    int v = (t < nb) ? bsum[t] : 0;
    sh[t] = v;
    __syncthreads();
    #pragma unroll
    for (int off = 1; off < 256; off <<= 1) {
        int tmp = (t >= off) ? sh[t - off] : 0;
        __syncthreads();
        sh[t] += tmp;
        __syncthreads();
    }
    boff[t] = sh[t] - v;
}

__global__ void scan_add_kernel(int* __restrict__ row, const int* __restrict__ boff,
                                int* __restrict__ cur, int n)
{
    int g = blockIdx.x * blockDim.x + threadIdx.x;
    if (g < n) {
        int r = row[g] + boff[g >> 9];
        row[g] = r;
        cur[g] = r;
    }
}

__global__ void scatter_kernel(const int* __restrict__ src, const int* __restrict__ dst,
                               int* __restrict__ cur, int* __restrict__ csrc, int E)
{
    int e = blockIdx.x * blockDim.x + threadIdx.x;
    if (e < E) {
        int p = atomicAdd(&cur[dst[e]], 1);
        csrc[p] = src[e];
    }
}

// =====================================================================
// Attention: q fp32 (qs region 0), fused fp16 kv cache (ONE uint4 LDG
// per lane per edge = 4 k + 4 v values), skip fp32 (qs region 1).
// h-major warp mapping (head-phase L2 residency). LPE = C/4 lanes/edge,
// 32/LPE edges in flight. No online max (logits O(1)).
// =====================================================================
template <int LPE>
__global__ void attn_kernel(const float* __restrict__ qs,
                            const __half* __restrict__ kv,
                            const int* __restrict__ row,
                            const int* __restrict__ cnt,
                            const int* __restrict__ csrc,
                            float* __restrict__ dstb,
                            int H, float scale, int relu, int Nn)
{
    constexpr int EPW = 32 / LPE;
    constexpr int C   = LPE * 4;

    int w    = (blockIdx.x * blockDim.x + threadIdx.x) >> 5;
    int lane = threadIdx.x & 31;
    if (w >= Nn * H) return;
    int h = w / Nn;            // h-major
    int n = w - h * Nn;
    const int HC = H * C;
    int sl  = lane & (LPE - 1);
    int sub = lane / LPE;

    float4 q4 = *(const float4*)&qs[(size_t)n * 2 * HC + h * C + sl * 4];
    q4.x *= scale; q4.y *= scale; q4.z *= scale; q4.w *= scale;

    int start = row[n];
    int deg   = cnt[n];

    float  l = 0.f;
    float4 acc = make_float4(0.f, 0.f, 0.f, 0.f);

    for (int base = 0; base < deg; base += 32) {
        int nb = min(32, deg - base);
        int sp = (lane < nb) ? __ldg(&csrc[start + base + lane]) : 0;
        for (int g = 0; g * EPW < nb; g++) {
            int  slot  = g * EPW + sub;
            bool valid = slot < nb;
            int  s     = __shfl_sync(0xffffffffu, sp, slot & 31);
            // one 16B load: {k[4sl..+3], v[4sl..+3]} fp16
            uint4 raw = __ldg((const uint4*)&kv[((size_t)s * H + h) * 2 * C + sl * 8]);
            float2 k01 = h2f(raw.x), k23 = h2f(raw.y);
            float2 v01 = h2f(raw.z), v23 = h2f(raw.w);

            float dot = q4.x * k01.x;
            dot = fmaf(q4.y, k01.y, dot);
            dot = fmaf(q4.z, k23.x, dot);
            dot = fmaf(q4.w, k23.y, dot);
            #pragma unroll
            for (int o = 1; o < LPE; o <<= 1)
                dot += __shfl_xor_sync(0xffffffffu, dot, o);

            float p = valid ? __expf(dot) : 0.f;
            l += p;
            acc.x = fmaf(p, v01.x, acc.x);
            acc.y = fmaf(p, v01.y, acc.y);
            acc.z = fmaf(p, v23.x, acc.z);
            acc.w = fmaf(p, v23.y, acc.w);
        }
    }

    #pragma unroll
    for (int o = LPE; o < 32; o <<= 1) {
        l     += __shfl_xor_sync(0xffffffffu, l, o);
        acc.x += __shfl_xor_sync(0xffffffffu, acc.x, o);
        acc.y += __shfl_xor_sync(0xffffffffu, acc.y, o);
        acc.z += __shfl_xor_sync(0xffffffffu, acc.z, o);
        acc.w += __shfl_xor_sync(0xffffffffu, acc.w, o);
    }

    float inv = 1.0f / (l + 1e-16f);
    if (lane < LPE) {
        float4 o4 = *(const float4*)&qs[(size_t)n * 2 * HC + HC + h * C + lane * 4];
        o4.x += acc.x * inv;
        o4.y += acc.y * inv;
        o4.z += acc.z * inv;
        o4.w += acc.w * inv;
        if (relu) {
            o4.x = fmaxf(o4.x, 0.f);
            o4.y = fmaxf(o4.y, 0.f);
            o4.z = fmaxf(o4.z, 0.f);
            o4.w = fmaxf(o4.w, 0.f);
        }
        *(float4*)&dstb[(size_t)n * HC + h * C + lane * 4] = o4;
    }
}

// =====================================================================
// Host-side orchestration
// =====================================================================
static void* sym_addr(const void* symbol)
{
    void* p = nullptr;
    cudaGetSymbolAddress(&p, symbol);
    return p;
}

static void launch_attn(const float* qs, const __half* kv,
                        const int* row, const int* cnt, const int* csrc,
                        float* dstb, int N, int H, int C, bool relu)
{
    int NH = N * H;
    int blocks = (NH * 32 + 255) / 256;
    float scale = 1.0f / sqrtf((float)C);
    if (C == 32)
        attn_kernel<8><<<blocks, 256>>>(qs, kv, row, cnt, csrc, dstb, H, scale, relu ? 1 : 0, N);
    else
        attn_kernel<16><<<blocks, 256>>>(qs, kv, row, cnt, csrc, dstb, H, scale, relu ? 1 : 0, N);
}

extern "C" void kernel_launch(void* const* d_in, const int* in_sizes, int n_in,
                              void* d_out, int out_size)
{
    const float* x  = (const float*)d_in[0];
    const int*   ei = (const int*)d_in[1];
    const int N = in_sizes[0] / 64;
    const int E = in_sizes[1] / 2;
    const int* src = ei;
    const int* dst = ei + E;

    const float* W[24];
    for (int i = 0; i < 24; i++) W[i] = (const float*)d_in[2 + i];

    float*  qs  = (float*)sym_addr(g_qs);
    __half* kv  = (__half*)sym_addr(g_kv);
    float* h1   = (float*)sym_addr(g_h1);
    float* h2   = (float*)sym_addr(g_h2);
    float* wp   = (float*)sym_addr(g_wp);
    float* bp   = (float*)sym_addr(g_bp);
    int*   cnt  = (int*)sym_addr(g_cnt);
    int*   row  = (int*)sym_addr(g_row);
    int*   cur  = (int*)sym_addr(g_cur);
    int*   bsum = (int*)sym_addr(g_bsum);
    int*   boff = (int*)sym_addr(g_boff);
    int*   csrc = (int*)sym_addr(g_csrc);
    float* out  = (float*)d_out;

    float* wp1 = wp;            float* bp1 = bp;
    float* wp2 = wp + 57344;    float* bp2 = bp + 896;
    float* wp3 = wp + 172032;   float* bp3 = bp + 1408;

    int nscan = (N + 511) / 512;

    // launch order keeps layer-1 GEMM in the ncu capture slot (#4)
    pack_w<<<(64 * 896 + 255) / 256, 256>>>(W[0], W[2], W[4], W[6], W[1], W[3], W[5], W[7],
                                            wp1, bp1, 64, 224);
    zero_cnt_kernel<<<(N + 255) / 256, 256>>>(cnt, N);
    hist_kernel<<<(E + 255) / 256, 256>>>(dst, cnt, E);

    // Layer 1 fused GEMM: [N,64] x [64,896]   (launch #4)
    {
        dim3 grid((N + 127) / 128, 896 / 128);
        gemm_bf16s<64, 224, 32><<<grid, 256>>>(x, wp1, bp1, qs, kv, N);
    }

    scan_block_kernel<<<nscan, 512>>>(cnt, row, bsum, N);
    scan_bsum_kernel<<<1, 256>>>(bsum, boff, nscan);
    scan_add_kernel<<<(N + 255) / 256, 256>>>(row, boff, cur, N);
    scatter_kernel<<<(E + 255) / 256, 256>>>(src, dst, cur, csrc, E);
    pack_w<<<(224 * 512 + 255) / 256, 256>>>(W[8], W[10], W[12], W[14], W[9], W[11], W[13], W[15],
                                             wp2, bp2, 224, 128);
    pack_w<<<(128 * 256 + 255) / 256, 256>>>(W[16], W[18], W[20], W[22], W[17], W[19], W[21], W[23],
                                             wp3, bp3, 128, 64);

    // Layer 1 attn: H=7, C=32, relu -> h1
    launch_attn(qs, kv, row, cnt, csrc, h1, N, 7, 32, true);

    // Layer 2: [N,224] x [224,512]
    {
        dim3 grid((N + 127) / 128, 512 / 128);
        gemm_bf16s<224, 128, 32><<<grid, 256>>>(h1, wp2, bp2, qs, kv, N);
    }
    launch_attn(qs, kv, row, cnt, csrc, h2, N, 4, 32, true);

    // Layer 3: [N,128] x [128,256]
    {
        dim3 grid((N + 127) / 128, 256 / 128);
        gemm_bf16s<128, 64, 64><<<grid, 256>>>(h2, wp3, bp3, qs, kv, N);
    }
    launch_attn(qs, kv, row, cnt, csrc, out, N, 1, 64, false);
}

// round 13
// speedup vs baseline: 1.2170x; 1.0176x over previous
#include <cuda_runtime.h>
#include <cuda_bf16.h>
#include <cuda_fp16.h>
#include <math.h>

#define NN 100000
#define EE 800000

// ---------------- scratch (device globals; no allocations) ----------------
__device__ float  g_qs[NN * 448];           // fp32 q|skip  [N, 2*HC]
__device__ __half g_kv[NN * 448];           // fp16 fused kv [N*H, 2*C] chunked
__device__ float  g_h1[NN * 224];
__device__ float  g_h2[NN * 128];
__device__ float  g_wp[204800];             // packed weights, 3 layers
__device__ float  g_bp[1664];               // packed biases
// CSR scratch
__device__ int g_cnt[NN];
__device__ int g_row[NN + 1];
__device__ int g_cur[NN];
__device__ int g_bsum[256];
__device__ int g_boff[256];
__device__ int g_csrc[EE];

// ---------------- helpers ---------------------------------------------------
__device__ __forceinline__ void split_pack(float a, float b, unsigned& hi, unsigned& lo)
{
    __nv_bfloat16 ha = __float2bfloat16(a);
    __nv_bfloat16 hb = __float2bfloat16(b);
    __nv_bfloat16 la = __float2bfloat16(a - __bfloat162float(ha));
    __nv_bfloat16 lb = __float2bfloat16(b - __bfloat162float(hb));
    __nv_bfloat162 h2 = __halves2bfloat162(ha, hb);
    __nv_bfloat162 l2 = __halves2bfloat162(la, lb);
    hi = *(unsigned*)&h2;
    lo = *(unsigned*)&l2;
}

__device__ __forceinline__ void mma_bf16(float4& d, const unsigned a[4], const unsigned b[2])
{
    asm volatile("mma.sync.aligned.m16n8k16.row.col.f32.bf16.bf16.f32 "
                 "{%0,%1,%2,%3}, {%4,%5,%6,%7}, {%8,%9}, {%0,%1,%2,%3};"
                 : "+f"(d.x), "+f"(d.y), "+f"(d.z), "+f"(d.w)
                 : "r"(a[0]), "r"(a[1]), "r"(a[2]), "r"(a[3]),
                   "r"(b[0]), "r"(b[1]));
}

__device__ __forceinline__ void ldsm4(unsigned a[4], unsigned addr)
{
    asm volatile("ldmatrix.sync.aligned.m8n8.x4.shared.b16 {%0,%1,%2,%3}, [%4];"
                 : "=r"(a[0]), "=r"(a[1]), "=r"(a[2]), "=r"(a[3]) : "r"(addr));
}

__device__ __forceinline__ float2 h2f(unsigned u)
{
    return __half22float2(*reinterpret_cast<__half2*>(&u));
}

// =====================================================================
// Weight pack: Wp[kk][j*HC + c] = Wj[kk][c]; bp[j*HC + c] = bj[c]
// =====================================================================
__global__ void pack_w(const float* __restrict__ Wq, const float* __restrict__ Wk,
                       const float* __restrict__ Wv, const float* __restrict__ Ws,
                       const float* __restrict__ bq, const float* __restrict__ bk,
                       const float* __restrict__ bv, const float* __restrict__ bs,
                       float* __restrict__ Wp, float* __restrict__ bp,
                       int din, int HC)
{
    int i = blockIdx.x * blockDim.x + threadIdx.x;
    int tot = din * 4 * HC;
    if (i < tot) {
        int kk  = i / (4 * HC);
        int rem = i - kk * 4 * HC;
        int j   = rem / HC;
        int c   = rem - j * HC;
        const float* Wj = (j == 0) ? Wq : (j == 1) ? Wk : (j == 2) ? Wv : Ws;
        Wp[i] = Wj[kk * HC + c];
    }
    if (i < 4 * HC) {
        int j = i / HC, c = i - j * HC;
        const float* bj = (j == 0) ? bq : (j == 1) ? bk : (j == 2) ? bv : bs;
        bp[i] = bj[c];
    }
}

// =====================================================================
// GEMM: X[N,DIN] @ Wp[DIN, 4*HC] + bp, routed epilogue:
//   region 0 (q) -> qs fp32 | 1 (k) -> kv fp16 | 2 (v) -> kv fp16 | 3 (s) -> qs
// kv layout: [(row*H + h)*2C] in 16B chunks {k[4j..4j+3], v[4j..4j+3]}.
// bf16 3-term split, BM=128, BN=128, BK=16, warp tile 64x32, ldmatrix A.
// =====================================================================
template <int DIN, int HC, int C>
__global__ void __launch_bounds__(256, 2)
gemm_bf16s(const float* __restrict__ X, const float* __restrict__ W,
           const float* __restrict__ bias,
           float* __restrict__ qs, __half* __restrict__ kv,
           int N)
{
    constexpr int BN   = 128;
    constexpr int BSTR = BN + 8;
    constexpr int DOUT = 4 * HC;
    constexpr int H    = HC / C;

    __shared__ unsigned sAhi[128][12];
    __shared__ unsigned sAlo[128][12];
    __shared__ unsigned sBhi[8][BSTR];
    __shared__ unsigned sBlo[8][BSTR];

    const int tid  = threadIdx.x;
    const int lane = tid & 31;
    const int warp = tid >> 5;
    const int wm   = (warp & 1) * 64;
    const int wn   = (warp >> 1) * 32;
    const int m0   = blockIdx.x * 128;
    const int n0   = blockIdx.y * BN;

    const int xr  = tid >> 1;
    const int xk  = (tid & 1) * 8;
    const int bpr = tid >> 5;            // B k-pair row 0..7
    const int bn0 = (tid & 31) * 4;

    float4 xreg0, xreg1, wreg0, wreg1;

    auto load_g = [&](int kb_) {
        int row = m0 + xr;
        if (row < N) {
            xreg0 = *(const float4*)&X[(size_t)row * DIN + kb_ + xk];
            xreg1 = *(const float4*)&X[(size_t)row * DIN + kb_ + xk + 4];
        } else {
            xreg0 = make_float4(0.f, 0.f, 0.f, 0.f);
            xreg1 = xreg0;
        }
        int col = n0 + bn0;
        wreg0 = *(const float4*)&W[(size_t)(kb_ + 2 * bpr) * DOUT + col];
        wreg1 = *(const float4*)&W[(size_t)(kb_ + 2 * bpr + 1) * DOUT + col];
    };

    auto store_smem = [&]() {
        uint4 hi4, lo4;
        split_pack(xreg0.x, xreg0.y, hi4.x, lo4.x);
        split_pack(xreg0.z, xreg0.w, hi4.y, lo4.y);
        split_pack(xreg1.x, xreg1.y, hi4.z, lo4.z);
        split_pack(xreg1.z, xreg1.w, hi4.w, lo4.w);
        *(uint4*)&sAhi[xr][xk >> 1] = hi4;
        *(uint4*)&sAlo[xr][xk >> 1] = lo4;
        split_pack(wreg0.x, wreg1.x, hi4.x, lo4.x);
        split_pack(wreg0.y, wreg1.y, hi4.y, lo4.y);
        split_pack(wreg0.z, wreg1.z, hi4.z, lo4.z);
        split_pack(wreg0.w, wreg1.w, hi4.w, lo4.w);
        *(uint4*)&sBhi[bpr][bn0] = hi4;
        *(uint4*)&sBlo[bpr][bn0] = lo4;
    };

    float4 d[4][4];
    #pragma unroll
    for (int i = 0; i < 4; i++)
        #pragma unroll
        for (int j = 0; j < 4; j++) d[i][j] = make_float4(0.f, 0.f, 0.f, 0.f);

    const int tg  = lane & 3;
    const int gid = lane >> 2;

    const int arow = (lane & 7) + ((lane >> 3) & 1) * 8;
    const int akp  = (lane >> 4) * 4;
    const unsigned offA = ((wm + arow) * 12 + akp) * 4;
    const unsigned addrAhi = (unsigned)__cvta_generic_to_shared(&sAhi[0][0]) + offA;
    const unsigned addrAlo = (unsigned)__cvta_generic_to_shared(&sAlo[0][0]) + offA;

    load_g(0);
    #pragma unroll 1
    for (int kb = 0; kb < DIN; kb += 16) {
        store_smem();
        __syncthreads();
        if (kb + 16 < DIN) load_g(kb + 16);

        unsigned bh[4][2], bl[4][2];
        #pragma unroll
        for (int in = 0; in < 4; in++) {
            int bc = wn + gid + in * 8;
            bh[in][0] = sBhi[tg][bc];
            bh[in][1] = sBhi[tg + 4][bc];
            bl[in][0] = sBlo[tg][bc];
            bl[in][1] = sBlo[tg + 4][bc];
        }
        #pragma unroll
        for (int im = 0; im < 4; im++) {
            unsigned ah[4], al[4];
            ldsm4(ah, addrAhi + im * 768);
            ldsm4(al, addrAlo + im * 768);
            #pragma unroll
            for (int in = 0; in < 4; in++) {
                mma_bf16(d[im][in], ah, bh[in]);
                mma_bf16(d[im][in], ah, bl[in]);
                mma_bf16(d[im][in], al, bh[in]);
            }
        }
        __syncthreads();
    }

    // --- routed epilogue (routing arithmetic compile-time strength-reduced)
    #pragma unroll
    for (int im = 0; im < 4; im++) {
        int row0 = m0 + wm + im * 16 + gid;
        #pragma unroll
        for (int in = 0; in < 4; in++) {
            int col = n0 + wn + in * 8 + tg * 2;
            float b0 = __ldg(&bias[col]);
            float b1 = __ldg(&bias[col + 1]);
            int reg = col / HC;           // col even, HC even -> pair same region
            int c   = col - reg * HC;
            #pragma unroll
            for (int half = 0; half < 2; half++) {
                int row = row0 + half * 8;
                if (row >= N) continue;
                float2 o = half ? make_float2(d[im][in].z + b0, d[im][in].w + b1)
                                : make_float2(d[im][in].x + b0, d[im][in].y + b1);
                if (reg == 0) {
                    *(float2*)&qs[(size_t)row * 2 * HC + c] = o;
                } else if (reg == 3) {
                    *(float2*)&qs[(size_t)row * 2 * HC + HC + c] = o;
                } else {
                    int h  = c / C;
                    int ch = c - h * C;
                    size_t base = ((size_t)row * H + h) * 2 * C
                                + (ch >> 2) * 8 + (ch & 3) + (reg == 2 ? 4 : 0);
                    *(__half2*)&kv[base] = __float22half2_rn(o);
                }
            }
        }
    }
}

// =====================================================================
// CSR build
// =====================================================================
__global__ void zero_cnt_kernel(int* __restrict__ cnt, int n)
{
    int i = blockIdx.x * blockDim.x + threadIdx.x;
    if (i < n) cnt[i] = 0;
}

__global__ void hist_kernel(const int* __restrict__ dst, int* __restrict__ cnt, int E)
{
    int e = blockIdx.x * blockDim.x + threadIdx.x;
    if (e < E) atomicAdd(&cnt[dst[e]], 1);
}

__global__ void scan_block_kernel(const int* __restrict__ cnt,
                                  int* __restrict__ row,
                                  int* __restrict__ bsum, int n)
{
    __shared__ int sh[512];
    int t = threadIdx.x;
    int g = blockIdx.x * 512 + t;
    int v = (g < n) ? cnt[g] : 0;
    sh[t] = v;
    __syncthreads();
    #pragma unroll
    for (int off = 1; off < 512; off <<= 1) {
        int tmp = (t >= off) ? sh[t - off] : 0;
        __syncthreads();
        sh[t] += tmp;
        __syncthreads();
    }
    if (g < n) row[g] = sh[t] - v;
    if (t == 511) bsum[blockIdx.x] = sh[511];
}

__global__ void scan_bsum_kernel(const int* __restrict__ bsum,
                                 int* __restrict__ boff, int nb)
{
    __shared__ int sh[256];
    int t = threadIdx.x;
    int v = (t < nb) ? bsum[t] : 0;
    sh[t] = v;
    __syncthreads();
    #pragma unroll
    for (int off = 1; off < 256; off <<= 1) {
        int tmp = (t >= off) ? sh[t - off] : 0;
        __syncthreads();
        sh[t] += tmp;
        __syncthreads();
    }
    boff[t] = sh[t] - v;
}

__global__ void scan_add_kernel(int* __restrict__ row, const int* __restrict__ boff,
                                int* __restrict__ cur, int n)
{
    int g = blockIdx.x * blockDim.x + threadIdx.x;
    if (g < n) {
        int r = row[g] + boff[g >> 9];
        row[g] = r;
        cur[g] = r;
    }
}

__global__ void scatter_kernel(const int* __restrict__ src, const int* __restrict__ dst,
                               int* __restrict__ cur, int* __restrict__ csrc, int E)
{
    int e = blockIdx.x * blockDim.x + threadIdx.x;
    if (e < E) {
        int p = atomicAdd(&cur[dst[e]], 1);
        csrc[p] = src[e];
    }
}

// =====================================================================
// Attention: q fp32 (qs region 0), fused fp16 kv cache, skip fp32.
// h-major warp mapping. LPE = C/4 lanes/edge, 32/LPE edges in flight.
// SOFTWARE-PIPELINED gather loop (depth 2): the kv LDG for group g+1
// is issued before computing group g, overlapping the ~300-600 cyc
// long-scoreboard wait with compute. exp via exp2f with log2(e)*scale
// folded into q.
// =====================================================================
template <int LPE>
__global__ void attn_kernel(const float* __restrict__ qs,
                            const __half* __restrict__ kv,
                            const int* __restrict__ row,
                            const int* __restrict__ cnt,
                            const int* __restrict__ csrc,
                            float* __restrict__ dstb,
                            int H, float scale, int relu, int Nn)
{
    constexpr int EPW = 32 / LPE;
    constexpr int C   = LPE * 4;

    int w    = (blockIdx.x * blockDim.x + threadIdx.x) >> 5;
    int lane = threadIdx.x & 31;
    if (w >= Nn * H) return;
    int h = w / Nn;            // h-major
    int n = w - h * Nn;
    const int HC = H * C;
    int sl  = lane & (LPE - 1);
    int sub = lane / LPE;

    float4 q4 = *(const float4*)&qs[(size_t)n * 2 * HC + h * C + sl * 4];
    float qsc = scale * 1.44269504089f;     // fold log2(e): exp(x) = exp2(x*log2 e)
    q4.x *= qsc; q4.y *= qsc; q4.z *= qsc; q4.w *= qsc;

    int start = row[n];
    int deg   = cnt[n];

    float  l = 0.f;
    float4 acc = make_float4(0.f, 0.f, 0.f, 0.f);

    for (int base = 0; base < deg; base += 32) {
        int nb = min(32, deg - base);
        int sp = (lane < nb) ? __ldg(&csrc[start + base + lane]) : 0;
        int ng = (nb + EPW - 1) / EPW;

        // prologue: issue load for group 0
        int s0 = __shfl_sync(0xffffffffu, sp, sub & 31);
        uint4 raw = __ldg((const uint4*)&kv[((size_t)s0 * H + h) * 2 * C + sl * 8]);

        for (int g = 0; g < ng; g++) {
            uint4 cur   = raw;
            bool  valid = (g * EPW + sub) < nb;
            if (g + 1 < ng) {   // issue next gather BEFORE computing current
                int s1 = __shfl_sync(0xffffffffu, sp, ((g + 1) * EPW + sub) & 31);
                raw = __ldg((const uint4*)&kv[((size_t)s1 * H + h) * 2 * C + sl * 8]);
            }

            float2 k01 = h2f(cur.x), k23 = h2f(cur.y);
            float2 v01 = h2f(cur.z), v23 = h2f(cur.w);

            float dot = q4.x * k01.x;
            dot = fmaf(q4.y, k01.y, dot);
            dot = fmaf(q4.z, k23.x, dot);
            dot = fmaf(q4.w, k23.y, dot);
            #pragma unroll
            for (int o = 1; o < LPE; o <<= 1)
                dot += __shfl_xor_sync(0xffffffffu, dot, o);

            float p = valid ? exp2f(dot) : 0.f;
            l += p;
            acc.x = fmaf(p, v01.x, acc.x);
            acc.y = fmaf(p, v01.y, acc.y);
            acc.z = fmaf(p, v23.x, acc.z);
            acc.w = fmaf(p, v23.y, acc.w);
        }
    }

    #pragma unroll
    for (int o = LPE; o < 32; o <<= 1) {
        l     += __shfl_xor_sync(0xffffffffu, l, o);
        acc.x += __shfl_xor_sync(0xffffffffu, acc.x, o);
        acc.y += __shfl_xor_sync(0xffffffffu, acc.y, o);
        acc.z += __shfl_xor_sync(0xffffffffu, acc.z, o);
        acc.w += __shfl_xor_sync(0xffffffffu, acc.w, o);
    }

    float inv = 1.0f / (l + 1e-16f);
    if (lane < LPE) {
        float4 o4 = *(const float4*)&qs[(size_t)n * 2 * HC + HC + h * C + lane * 4];
        o4.x += acc.x * inv;
        o4.y += acc.y * inv;
        o4.z += acc.z * inv;
        o4.w += acc.w * inv;
        if (relu) {
            o4.x = fmaxf(o4.x, 0.f);
            o4.y = fmaxf(o4.y, 0.f);
            o4.z = fmaxf(o4.z, 0.f);
            o4.w = fmaxf(o4.w, 0.f);
        }
        *(float4*)&dstb[(size_t)n * HC + h * C + lane * 4] = o4;
    }
}

// =====================================================================
// Host-side orchestration
// =====================================================================
static void* sym_addr(const void* symbol)
{
    void* p = nullptr;
    cudaGetSymbolAddress(&p, symbol);
    return p;
}

static void launch_attn(const float* qs, const __half* kv,
                        const int* row, const int* cnt, const int* csrc,
                        float* dstb, int N, int H, int C, bool relu)
{
    int NH = N * H;
    int blocks = (NH * 32 + 255) / 256;
    float scale = 1.0f / sqrtf((float)C);
    if (C == 32)
        attn_kernel<8><<<blocks, 256>>>(qs, kv, row, cnt, csrc, dstb, H, scale, relu ? 1 : 0, N);
    else
        attn_kernel<16><<<blocks, 256>>>(qs, kv, row, cnt, csrc, dstb, H, scale, relu ? 1 : 0, N);
}

extern "C" void kernel_launch(void* const* d_in, const int* in_sizes, int n_in,
                              void* d_out, int out_size)
{
    const float* x  = (const float*)d_in[0];
    const int*   ei = (const int*)d_in[1];
    const int N = in_sizes[0] / 64;
    const int E = in_sizes[1] / 2;
    const int* src = ei;
    const int* dst = ei + E;

    const float* W[24];
    for (int i = 0; i < 24; i++) W[i] = (const float*)d_in[2 + i];

    float*  qs  = (float*)sym_addr(g_qs);
    __half* kv  = (__half*)sym_addr(g_kv);
    float* h1   = (float*)sym_addr(g_h1);
    float* h2   = (float*)sym_addr(g_h2);
    float* wp   = (float*)sym_addr(g_wp);
    float* bp   = (float*)sym_addr(g_bp);
    int*   cnt  = (int*)sym_addr(g_cnt);
    int*   row  = (int*)sym_addr(g_row);
    int*   cur  = (int*)sym_addr(g_cur);
    int*   bsum = (int*)sym_addr(g_bsum);
    int*   boff = (int*)sym_addr(g_boff);
    int*   csrc = (int*)sym_addr(g_csrc);
    float* out  = (float*)d_out;

    float* wp1 = wp;            float* bp1 = bp;
    float* wp2 = wp + 57344;    float* bp2 = bp + 896;
    float* wp3 = wp + 172032;   float* bp3 = bp + 1408;

    int nscan = (N + 511) / 512;

    // launch order keeps layer-1 GEMM in the ncu capture slot (#4)
    pack_w<<<(64 * 896 + 255) / 256, 256>>>(W[0], W[2], W[4], W[6], W[1], W[3], W[5], W[7],
                                            wp1, bp1, 64, 224);
    zero_cnt_kernel<<<(N + 255) / 256, 256>>>(cnt, N);
    hist_kernel<<<(E + 255) / 256, 256>>>(dst, cnt, E);

    // Layer 1 fused GEMM: [N,64] x [64,896]   (launch #4)
    {
        dim3 grid((N + 127) / 128, 896 / 128);
        gemm_bf16s<64, 224, 32><<<grid, 256>>>(x, wp1, bp1, qs, kv, N);
    }

    scan_block_kernel<<<nscan, 512>>>(cnt, row, bsum, N);
    scan_bsum_kernel<<<1, 256>>>(bsum, boff, nscan);
    scan_add_kernel<<<(N + 255) / 256, 256>>>(row, boff, cur, N);
    scatter_kernel<<<(E + 255) / 256, 256>>>(src, dst, cur, csrc, E);
    pack_w<<<(224 * 512 + 255) / 256, 256>>>(W[8], W[10], W[12], W[14], W[9], W[11], W[13], W[15],
                                             wp2, bp2, 224, 128);
    pack_w<<<(128 * 256 + 255) / 256, 256>>>(W[16], W[18], W[20], W[22], W[17], W[19], W[21], W[23],
                                             wp3, bp3, 128, 64);

    // Layer 1 attn: H=7, C=32, relu -> h1
    launch_attn(qs, kv, row, cnt, csrc, h1, N, 7, 32, true);

    // Layer 2: [N,224] x [224,512]
    {
        dim3 grid((N + 127) / 128, 512 / 128);
        gemm_bf16s<224, 128, 32><<<grid, 256>>>(h1, wp2, bp2, qs, kv, N);
    }
    launch_attn(qs, kv, row, cnt, csrc, h2, N, 4, 32, true);

    // Layer 3: [N,128] x [128,256]
    {
        dim3 grid((N + 127) / 128, 256 / 128);
        gemm_bf16s<128, 64, 64><<<grid, 256>>>(h2, wp3, bp3, qs, kv, N);
    }
    launch_attn(qs, kv, row, cnt, csrc, out, N, 1, 64, false);
}

// round 14
// speedup vs baseline: 1.2802x; 1.0520x over previous
#include <cuda_runtime.h>
#include <cuda_bf16.h>
#include <cuda_fp16.h>
#include <math.h>

#define NN 100000
#define EE 800000

// ---------------- scratch (device globals; no allocations) ----------------
__device__ float  g_qs[NN * 448];           // fp32 q|skip  [N, 2*HC]
__device__ __half g_kv[NN * 448];           // fp16 fused kv [N*H, 2*C] chunked
__device__ float  g_h1[NN * 224];
__device__ float  g_h2[NN * 128];
__device__ float  g_wp[204800];             // packed weights, 3 layers
__device__ float  g_bp[1664];               // packed biases
// CSR scratch
__device__ int g_cnt[NN];
__device__ int g_row[NN + 1];
__device__ int g_cur[NN];
__device__ int g_bsum[256];
__device__ int g_boff[256];
__device__ int g_csrc[EE];

// ---------------- helpers ---------------------------------------------------
__device__ __forceinline__ void split_pack(float a, float b, unsigned& hi, unsigned& lo)
{
    __nv_bfloat16 ha = __float2bfloat16(a);
    __nv_bfloat16 hb = __float2bfloat16(b);
    __nv_bfloat16 la = __float2bfloat16(a - __bfloat162float(ha));
    __nv_bfloat16 lb = __float2bfloat16(b - __bfloat162float(hb));
    __nv_bfloat162 h2 = __halves2bfloat162(ha, hb);
    __nv_bfloat162 l2 = __halves2bfloat162(la, lb);
    hi = *(unsigned*)&h2;
    lo = *(unsigned*)&l2;
}

__device__ __forceinline__ void mma_bf16(float4& d, const unsigned a[4], const unsigned b[2])
{
    asm volatile("mma.sync.aligned.m16n8k16.row.col.f32.bf16.bf16.f32 "
                 "{%0,%1,%2,%3}, {%4,%5,%6,%7}, {%8,%9}, {%0,%1,%2,%3};"
                 : "+f"(d.x), "+f"(d.y), "+f"(d.z), "+f"(d.w)
                 : "r"(a[0]), "r"(a[1]), "r"(a[2]), "r"(a[3]),
                   "r"(b[0]), "r"(b[1]));
}

__device__ __forceinline__ void ldsm4(unsigned a[4], unsigned addr)
{
    asm volatile("ldmatrix.sync.aligned.m8n8.x4.shared.b16 {%0,%1,%2,%3}, [%4];"
                 : "=r"(a[0]), "=r"(a[1]), "=r"(a[2]), "=r"(a[3]) : "r"(addr));
}

__device__ __forceinline__ float2 h2f(unsigned u)
{
    return __half22float2(*reinterpret_cast<__half2*>(&u));
}

__device__ __forceinline__ float ex2_approx(float x)
{
    float r;
    asm("ex2.approx.ftz.f32 %0, %1;" : "=f"(r) : "f"(x));
    return r;
}

// =====================================================================
// Weight pack: Wp[kk][j*HC + c] = Wj[kk][c]; bp[j*HC + c] = bj[c]
// =====================================================================
__global__ void pack_w(const float* __restrict__ Wq, const float* __restrict__ Wk,
                       const float* __restrict__ Wv, const float* __restrict__ Ws,
                       const float* __restrict__ bq, const float* __restrict__ bk,
                       const float* __restrict__ bv, const float* __restrict__ bs,
                       float* __restrict__ Wp, float* __restrict__ bp,
                       int din, int HC)
{
    int i = blockIdx.x * blockDim.x + threadIdx.x;
    int tot = din * 4 * HC;
    if (i < tot) {
        int kk  = i / (4 * HC);
        int rem = i - kk * 4 * HC;
        int j   = rem / HC;
        int c   = rem - j * HC;
        const float* Wj = (j == 0) ? Wq : (j == 1) ? Wk : (j == 2) ? Wv : Ws;
        Wp[i] = Wj[kk * HC + c];
    }
    if (i < 4 * HC) {
        int j = i / HC, c = i - j * HC;
        const float* bj = (j == 0) ? bq : (j == 1) ? bk : (j == 2) ? bv : bs;
        bp[i] = bj[c];
    }
}

// =====================================================================
// GEMM: X[N,DIN] @ Wp[DIN, 4*HC] + bp, routed epilogue:
//   region 0 (q) -> qs fp32 | 1 (k) -> kv fp16 | 2 (v) -> kv fp16 | 3 (s) -> qs
// kv layout: [(row*H + h)*2C] in 16B chunks {k[4j..4j+3], v[4j..4j+3]}.
// bf16 3-term split, BM=128, BN=128, BK=16, warp tile 64x32, ldmatrix A.
// =====================================================================
template <int DIN, int HC, int C>
__global__ void __launch_bounds__(256, 2)
gemm_bf16s(const float* __restrict__ X, const float* __restrict__ W,
           const float* __restrict__ bias,
           float* __restrict__ qs, __half* __restrict__ kv,
           int N)
{
    constexpr int BN   = 128;
    constexpr int BSTR = BN + 8;
    constexpr int DOUT = 4 * HC;
    constexpr int H    = HC / C;

    __shared__ unsigned sAhi[128][12];
    __shared__ unsigned sAlo[128][12];
    __shared__ unsigned sBhi[8][BSTR];
    __shared__ unsigned sBlo[8][BSTR];

    const int tid  = threadIdx.x;
    const int lane = tid & 31;
    const int warp = tid >> 5;
    const int wm   = (warp & 1) * 64;
    const int wn   = (warp >> 1) * 32;
    const int m0   = blockIdx.x * 128;
    const int n0   = blockIdx.y * BN;

    const int xr  = tid >> 1;
    const int xk  = (tid & 1) * 8;
    const int bpr = tid >> 5;            // B k-pair row 0..7
    const int bn0 = (tid & 31) * 4;

    float4 xreg0, xreg1, wreg0, wreg1;

    auto load_g = [&](int kb_) {
        int row = m0 + xr;
        if (row < N) {
            xreg0 = *(const float4*)&X[(size_t)row * DIN + kb_ + xk];
            xreg1 = *(const float4*)&X[(size_t)row * DIN + kb_ + xk + 4];
        } else {
            xreg0 = make_float4(0.f, 0.f, 0.f, 0.f);
            xreg1 = xreg0;
        }
        int col = n0 + bn0;
        wreg0 = *(const float4*)&W[(size_t)(kb_ + 2 * bpr) * DOUT + col];
        wreg1 = *(const float4*)&W[(size_t)(kb_ + 2 * bpr + 1) * DOUT + col];
    };

    auto store_smem = [&]() {
        uint4 hi4, lo4;
        split_pack(xreg0.x, xreg0.y, hi4.x, lo4.x);
        split_pack(xreg0.z, xreg0.w, hi4.y, lo4.y);
        split_pack(xreg1.x, xreg1.y, hi4.z, lo4.z);
        split_pack(xreg1.z, xreg1.w, hi4.w, lo4.w);
        *(uint4*)&sAhi[xr][xk >> 1] = hi4;
        *(uint4*)&sAlo[xr][xk >> 1] = lo4;
        split_pack(wreg0.x, wreg1.x, hi4.x, lo4.x);
        split_pack(wreg0.y, wreg1.y, hi4.y, lo4.y);
        split_pack(wreg0.z, wreg1.z, hi4.z, lo4.z);
        split_pack(wreg0.w, wreg1.w, hi4.w, lo4.w);
        *(uint4*)&sBhi[bpr][bn0] = hi4;
        *(uint4*)&sBlo[bpr][bn0] = lo4;
    };

    float4 d[4][4];
    #pragma unroll
    for (int i = 0; i < 4; i++)
        #pragma unroll
        for (int j = 0; j < 4; j++) d[i][j] = make_float4(0.f, 0.f, 0.f, 0.f);

    const int tg  = lane & 3;
    const int gid = lane >> 2;

    const int arow = (lane & 7) + ((lane >> 3) & 1) * 8;
    const int akp  = (lane >> 4) * 4;
    const unsigned offA = ((wm + arow) * 12 + akp) * 4;
    const unsigned addrAhi = (unsigned)__cvta_generic_to_shared(&sAhi[0][0]) + offA;
    const unsigned addrAlo = (unsigned)__cvta_generic_to_shared(&sAlo[0][0]) + offA;

    load_g(0);
    #pragma unroll 1
    for (int kb = 0; kb < DIN; kb += 16) {
        store_smem();
        __syncthreads();
        if (kb + 16 < DIN) load_g(kb + 16);

        unsigned bh[4][2], bl[4][2];
        #pragma unroll
        for (int in = 0; in < 4; in++) {
            int bc = wn + gid + in * 8;
            bh[in][0] = sBhi[tg][bc];
            bh[in][1] = sBhi[tg + 4][bc];
            bl[in][0] = sBlo[tg][bc];
            bl[in][1] = sBlo[tg + 4][bc];
        }
        #pragma unroll
        for (int im = 0; im < 4; im++) {
            unsigned ah[4], al[4];
            ldsm4(ah, addrAhi + im * 768);
            ldsm4(al, addrAlo + im * 768);
            #pragma unroll
            for (int in = 0; in < 4; in++) {
                mma_bf16(d[im][in], ah, bh[in]);
                mma_bf16(d[im][in], ah, bl[in]);
                mma_bf16(d[im][in], al, bh[in]);
            }
        }
        __syncthreads();
    }

    // --- routed epilogue (routing arithmetic compile-time strength-reduced)
    #pragma unroll
    for (int im = 0; im < 4; im++) {
        int row0 = m0 + wm + im * 16 + gid;
        #pragma unroll
        for (int in = 0; in < 4; in++) {
            int col = n0 + wn + in * 8 + tg * 2;
            float b0 = __ldg(&bias[col]);
            float b1 = __ldg(&bias[col + 1]);
            int reg = col / HC;           // col even, HC even -> pair same region
            int c   = col - reg * HC;
            #pragma unroll
            for (int half = 0; half < 2; half++) {
                int row = row0 + half * 8;
                if (row >= N) continue;
                float2 o = half ? make_float2(d[im][in].z + b0, d[im][in].w + b1)
                                : make_float2(d[im][in].x + b0, d[im][in].y + b1);
                if (reg == 0) {
                    *(float2*)&qs[(size_t)row * 2 * HC + c] = o;
                } else if (reg == 3) {
                    *(float2*)&qs[(size_t)row * 2 * HC + HC + c] = o;
                } else {
                    int h  = c / C;
                    int ch = c - h * C;
                    size_t base = ((size_t)row * H + h) * 2 * C
                                + (ch >> 2) * 8 + (ch & 3) + (reg == 2 ? 4 : 0);
                    *(__half2*)&kv[base] = __float22half2_rn(o);
                }
            }
        }
    }
}

// =====================================================================
// CSR build
// =====================================================================
__global__ void zero_cnt_kernel(int* __restrict__ cnt, int n)
{
    int i = blockIdx.x * blockDim.x + threadIdx.x;
    if (i < n) cnt[i] = 0;
}

__global__ void hist_kernel(const int* __restrict__ dst, int* __restrict__ cnt, int E)
{
    int e = blockIdx.x * blockDim.x + threadIdx.x;
    if (e < E) atomicAdd(&cnt[dst[e]], 1);
}

__global__ void scan_block_kernel(const int* __restrict__ cnt,
                                  int* __restrict__ row,
                                  int* __restrict__ bsum, int n)
{
    __shared__ int sh[512];
    int t = threadIdx.x;
    int g = blockIdx.x * 512 + t;
    int v = (g < n) ? cnt[g] : 0;
    sh[t] = v;
    __syncthreads();
    #pragma unroll
    for (int off = 1; off < 512; off <<= 1) {
        int tmp = (t >= off) ? sh[t - off] : 0;
        __syncthreads();
        sh[t] += tmp;
        __syncthreads();
    }
    if (g < n) row[g] = sh[t] - v;
    if (t == 511) bsum[blockIdx.x] = sh[511];
}

__global__ void scan_bsum_kernel(const int* __restrict__ bsum,
                                 int* __restrict__ boff, int nb)
{
    __shared__ int sh[256];
    int t = threadIdx.x;
    int v = (t < nb) ? bsum[t] : 0;
    sh[t] = v;
    __syncthreads();
    #pragma unroll
    for (int off = 1; off < 256; off <<= 1) {
        int tmp = (t >= off) ? sh[t - off] : 0;
        __syncthreads();
        sh[t] += tmp;
        __syncthreads();
    }
    boff[t] = sh[t] - v;
}

__global__ void scan_add_kernel(int* __restrict__ row, const int* __restrict__ boff,
                                int* __restrict__ cur, int n)
{
    int g = blockIdx.x * blockDim.x + threadIdx.x;
    if (g < n) {
        int r = row[g] + boff[g >> 9];
        row[g] = r;
        cur[g] = r;
    }
}

__global__ void scatter_kernel(const int* __restrict__ src, const int* __restrict__ dst,
                               int* __restrict__ cur, int* __restrict__ csrc, int E)
{
    int e = blockIdx.x * blockDim.x + threadIdx.x;
    if (e < E) {
        int p = atomicAdd(&cur[dst[e]], 1);
        csrc[p] = src[e];
    }
}

// =====================================================================
// Attention: q fp32 (qs region 0), fused fp16 kv cache, skip fp32.
// h-major warp mapping. LPE = C/4 lanes/edge, 32/LPE edges in flight.
// Depth-2 software-pipelined gather loop. exp via raw ex2.approx (MUFU)
// with log2(e)*scale folded into q. 64-thread blocks: fine-grained
// block retirement to kill the max-degree block-tail effect.
// =====================================================================
template <int LPE>
__global__ void attn_kernel(const float* __restrict__ qs,
                            const __half* __restrict__ kv,
                            const int* __restrict__ row,
                            const int* __restrict__ cnt,
                            const int* __restrict__ csrc,
                            float* __restrict__ dstb,
                            int H, float scale, int relu, int Nn)
{
    constexpr int EPW = 32 / LPE;
    constexpr int C   = LPE * 4;

    int w    = (blockIdx.x * blockDim.x + threadIdx.x) >> 5;
    int lane = threadIdx.x & 31;
    if (w >= Nn * H) return;
    int h = w / Nn;            // h-major
    int n = w - h * Nn;
    const int HC = H * C;
    int sl  = lane & (LPE - 1);
    int sub = lane / LPE;

    float4 q4 = *(const float4*)&qs[(size_t)n * 2 * HC + h * C + sl * 4];
    float qsc = scale * 1.44269504089f;     // exp(x) = exp2(x*log2 e)
    q4.x *= qsc; q4.y *= qsc; q4.z *= qsc; q4.w *= qsc;

    int start = row[n];
    int deg   = cnt[n];

    float  l = 0.f;
    float4 acc = make_float4(0.f, 0.f, 0.f, 0.f);

    for (int base = 0; base < deg; base += 32) {
        int nb = min(32, deg - base);
        int sp = (lane < nb) ? __ldg(&csrc[start + base + lane]) : 0;
        int ng = (nb + EPW - 1) / EPW;

        // prologue: issue load for group 0
        int s0 = __shfl_sync(0xffffffffu, sp, sub & 31);
        uint4 raw = __ldg((const uint4*)&kv[((size_t)s0 * H + h) * 2 * C + sl * 8]);

        for (int g = 0; g < ng; g++) {
            uint4 cur   = raw;
            bool  valid = (g * EPW + sub) < nb;
            if (g + 1 < ng) {   // issue next gather BEFORE computing current
                int s1 = __shfl_sync(0xffffffffu, sp, ((g + 1) * EPW + sub) & 31);
                raw = __ldg((const uint4*)&kv[((size_t)s1 * H + h) * 2 * C + sl * 8]);
            }

            float2 k01 = h2f(cur.x), k23 = h2f(cur.y);
            float2 v01 = h2f(cur.z), v23 = h2f(cur.w);

            float dot = q4.x * k01.x;
            dot = fmaf(q4.y, k01.y, dot);
            dot = fmaf(q4.z, k23.x, dot);
            dot = fmaf(q4.w, k23.y, dot);
            #pragma unroll
            for (int o = 1; o < LPE; o <<= 1)
                dot += __shfl_xor_sync(0xffffffffu, dot, o);

            float p = valid ? ex2_approx(dot) : 0.f;
            l += p;
            acc.x = fmaf(p, v01.x, acc.x);
            acc.y = fmaf(p, v01.y, acc.y);
            acc.z = fmaf(p, v23.x, acc.z);
            acc.w = fmaf(p, v23.y, acc.w);
        }
    }

    #pragma unroll
    for (int o = LPE; o < 32; o <<= 1) {
        l     += __shfl_xor_sync(0xffffffffu, l, o);
        acc.x += __shfl_xor_sync(0xffffffffu, acc.x, o);
        acc.y += __shfl_xor_sync(0xffffffffu, acc.y, o);
        acc.z += __shfl_xor_sync(0xffffffffu, acc.z, o);
        acc.w += __shfl_xor_sync(0xffffffffu, acc.w, o);
    }

    float inv = 1.0f / (l + 1e-16f);
    if (lane < LPE) {
        float4 o4 = *(const float4*)&qs[(size_t)n * 2 * HC + HC + h * C + lane * 4];
        o4.x += acc.x * inv;
        o4.y += acc.y * inv;
        o4.z += acc.z * inv;
        o4.w += acc.w * inv;
        if (relu) {
            o4.x = fmaxf(o4.x, 0.f);
            o4.y = fmaxf(o4.y, 0.f);
            o4.z = fmaxf(o4.z, 0.f);
            o4.w = fmaxf(o4.w, 0.f);
        }
        *(float4*)&dstb[(size_t)n * HC + h * C + lane * 4] = o4;
    }
}

// =====================================================================
// Host-side orchestration
// =====================================================================
static void* sym_addr(const void* symbol)
{
    void* p = nullptr;
    cudaGetSymbolAddress(&p, symbol);
    return p;
}

static void launch_attn(const float* qs, const __half* kv,
                        const int* row, const int* cnt, const int* csrc,
                        float* dstb, int N, int H, int C, bool relu)
{
    int NH = N * H;
    int blocks = (NH * 32 + 63) / 64;       // 64-thread blocks (2 warps)
    float scale = 1.0f / sqrtf((float)C);
    if (C == 32)
        attn_kernel<8><<<blocks, 64>>>(qs, kv, row, cnt, csrc, dstb, H, scale, relu ? 1 : 0, N);
    else
        attn_kernel<16><<<blocks, 64>>>(qs, kv, row, cnt, csrc, dstb, H, scale, relu ? 1 : 0, N);
}

extern "C" void kernel_launch(void* const* d_in, const int* in_sizes, int n_in,
                              void* d_out, int out_size)
{
    const float* x  = (const float*)d_in[0];
    const int*   ei = (const int*)d_in[1];
    const int N = in_sizes[0] / 64;
    const int E = in_sizes[1] / 2;
    const int* src = ei;
    const int* dst = ei + E;

    const float* W[24];
    for (int i = 0; i < 24; i++) W[i] = (const float*)d_in[2 + i];

    float*  qs  = (float*)sym_addr(g_qs);
    __half* kv  = (__half*)sym_addr(g_kv);
    float* h1   = (float*)sym_addr(g_h1);
    float* h2   = (float*)sym_addr(g_h2);
    float* wp   = (float*)sym_addr(g_wp);
    float* bp   = (float*)sym_addr(g_bp);
    int*   cnt  = (int*)sym_addr(g_cnt);
    int*   row  = (int*)sym_addr(g_row);
    int*   cur  = (int*)sym_addr(g_cur);
    int*   bsum = (int*)sym_addr(g_bsum);
    int*   boff = (int*)sym_addr(g_boff);
    int*   csrc = (int*)sym_addr(g_csrc);
    float* out  = (float*)d_out;

    float* wp1 = wp;            float* bp1 = bp;
    float* wp2 = wp + 57344;    float* bp2 = bp + 896;
    float* wp3 = wp + 172032;   float* bp3 = bp + 1408;

    int nscan = (N + 511) / 512;

    // launch order keeps layer-1 GEMM in the ncu capture slot (#4)
    pack_w<<<(64 * 896 + 255) / 256, 256>>>(W[0], W[2], W[4], W[6], W[1], W[3], W[5], W[7],
                                            wp1, bp1, 64, 224);
    zero_cnt_kernel<<<(N + 255) / 256, 256>>>(cnt, N);
    hist_kernel<<<(E + 255) / 256, 256>>>(dst, cnt, E);

    // Layer 1 fused GEMM: [N,64] x [64,896]   (launch #4)
    {
        dim3 grid((N + 127) / 128, 896 / 128);
        gemm_bf16s<64, 224, 32><<<grid, 256>>>(x, wp1, bp1, qs, kv, N);
    }

    scan_block_kernel<<<nscan, 512>>>(cnt, row, bsum, N);
    scan_bsum_kernel<<<1, 256>>>(bsum, boff, nscan);
    scan_add_kernel<<<(N + 255) / 256, 256>>>(row, boff, cur, N);
    scatter_kernel<<<(E + 255) / 256, 256>>>(src, dst, cur, csrc, E);
    pack_w<<<(224 * 512 + 255) / 256, 256>>>(W[8], W[10], W[12], W[14], W[9], W[11], W[13], W[15],
                                             wp2, bp2, 224, 128);
    pack_w<<<(128 * 256 + 255) / 256, 256>>>(W[16], W[18], W[20], W[22], W[17], W[19], W[21], W[23],
                                             wp3, bp3, 128, 64);

    // Layer 1 attn: H=7, C=32, relu -> h1
    launch_attn(qs, kv, row, cnt, csrc, h1, N, 7, 32, true);

    // Layer 2: [N,224] x [224,512]
    {
        dim3 grid((N + 127) / 128, 512 / 128);
        gemm_bf16s<224, 128, 32><<<grid, 256>>>(h1, wp2, bp2, qs, kv, N);
    }
    launch_attn(qs, kv, row, cnt, csrc, h2, N, 4, 32, true);

    // Layer 3: [N,128] x [128,256]
    {
        dim3 grid((N + 127) / 128, 256 / 128);
        gemm_bf16s<128, 64, 64><<<grid, 256>>>(h2, wp3, bp3, qs, kv, N);
    }
    launch_attn(qs, kv, row, cnt, csrc, out, N, 1, 64, false);
}

// round 15
// speedup vs baseline: 1.3321x; 1.0406x over previous
#include <cuda_runtime.h>
#include <cuda_bf16.h>
#include <cuda_fp16.h>
#include <math.h>

#define NN 100000
#define EE 800000

// ---------------- scratch (device globals; no allocations) ----------------
__device__ float  g_qs[NN * 448];           // fp32 q|skip  [N, 2*HC]
__device__ __half g_kv[NN * 448];           // fp16 fused kv [N*H, 2*C] chunked
__device__ float  g_h1[NN * 224];
__device__ float  g_h2[NN * 128];
__device__ float  g_wp[204800];             // packed weights, 3 layers
__device__ float  g_bp[1664];               // packed biases
// CSR scratch
__device__ int g_cnt[NN];
__device__ int g_row[NN + 1];
__device__ int g_cur[NN];
__device__ int g_bsum[256];
__device__ int g_boff[256];
__device__ int g_csrc[EE];

// ---------------- helpers ---------------------------------------------------
__device__ __forceinline__ void split_pack(float a, float b, unsigned& hi, unsigned& lo)
{
    __nv_bfloat16 ha = __float2bfloat16(a);
    __nv_bfloat16 hb = __float2bfloat16(b);
    __nv_bfloat16 la = __float2bfloat16(a - __bfloat162float(ha));
    __nv_bfloat16 lb = __float2bfloat16(b - __bfloat162float(hb));
    __nv_bfloat162 h2 = __halves2bfloat162(ha, hb);
    __nv_bfloat162 l2 = __halves2bfloat162(la, lb);
    hi = *(unsigned*)&h2;
    lo = *(unsigned*)&l2;
}

__device__ __forceinline__ void mma_bf16(float4& d, const unsigned a[4], const unsigned b[2])
{
    asm volatile("mma.sync.aligned.m16n8k16.row.col.f32.bf16.bf16.f32 "
                 "{%0,%1,%2,%3}, {%4,%5,%6,%7}, {%8,%9}, {%0,%1,%2,%3};"
                 : "+f"(d.x), "+f"(d.y), "+f"(d.z), "+f"(d.w)
                 : "r"(a[0]), "r"(a[1]), "r"(a[2]), "r"(a[3]),
                   "r"(b[0]), "r"(b[1]));
}

__device__ __forceinline__ void ldsm4(unsigned a[4], unsigned addr)
{
    asm volatile("ldmatrix.sync.aligned.m8n8.x4.shared.b16 {%0,%1,%2,%3}, [%4];"
                 : "=r"(a[0]), "=r"(a[1]), "=r"(a[2]), "=r"(a[3]) : "r"(addr));
}

__device__ __forceinline__ float2 h2f(unsigned u)
{
    return __half22float2(*reinterpret_cast<__half2*>(&u));
}

__device__ __forceinline__ float ex2_approx(float x)
{
    float r;
    asm("ex2.approx.ftz.f32 %0, %1;" : "=f"(r) : "f"(x));
    return r;
}

// =====================================================================
// Weight pack: Wp[kk][j*HC + c] = Wj[kk][c]; bp[j*HC + c] = bj[c]
// =====================================================================
__global__ void pack_w(const float* __restrict__ Wq, const float* __restrict__ Wk,
                       const float* __restrict__ Wv, const float* __restrict__ Ws,
                       const float* __restrict__ bq, const float* __restrict__ bk,
                       const float* __restrict__ bv, const float* __restrict__ bs,
                       float* __restrict__ Wp, float* __restrict__ bp,
                       int din, int HC)
{
    int i = blockIdx.x * blockDim.x + threadIdx.x;
    int tot = din * 4 * HC;
    if (i < tot) {
        int kk  = i / (4 * HC);
        int rem = i - kk * 4 * HC;
        int j   = rem / HC;
        int c   = rem - j * HC;
        const float* Wj = (j == 0) ? Wq : (j == 1) ? Wk : (j == 2) ? Wv : Ws;
        Wp[i] = Wj[kk * HC + c];
    }
    if (i < 4 * HC) {
        int j = i / HC, c = i - j * HC;
        const float* bj = (j == 0) ? bq : (j == 1) ? bk : (j == 2) ? bv : bs;
        bp[i] = bj[c];
    }
}

// =====================================================================
// GEMM: X[N,DIN] @ Wp[DIN, 4*HC] + bp, routed epilogue:
//   region 0 (q) -> qs fp32 | 1 (k) -> kv fp16 | 2 (v) -> kv fp16 | 3 (s) -> qs
// kv layout: [(row*H + h)*2C] in 16B chunks {k[4j..4j+3], v[4j..4j+3]}.
// bf16 3-term split, BM=128, BN=128, BK=16, warp tile 64x32, ldmatrix A.
// GRID: blockIdx.x = n-block (few), blockIdx.y = m-block -> consecutive
// CTAs reuse the same X tile across all n-blocks (X read from DRAM once).
// =====================================================================
template <int DIN, int HC, int C>
__global__ void __launch_bounds__(256, 2)
gemm_bf16s(const float* __restrict__ X, const float* __restrict__ W,
           const float* __restrict__ bias,
           float* __restrict__ qs, __half* __restrict__ kv,
           int N)
{
    constexpr int BN   = 128;
    constexpr int BSTR = BN + 8;
    constexpr int DOUT = 4 * HC;
    constexpr int H    = HC / C;

    __shared__ unsigned sAhi[128][12];
    __shared__ unsigned sAlo[128][12];
    __shared__ unsigned sBhi[8][BSTR];
    __shared__ unsigned sBlo[8][BSTR];

    const int tid  = threadIdx.x;
    const int lane = tid & 31;
    const int warp = tid >> 5;
    const int wm   = (warp & 1) * 64;
    const int wn   = (warp >> 1) * 32;
    const int m0   = blockIdx.y * 128;    // m on the SLOW axis
    const int n0   = blockIdx.x * BN;     // n on the FAST axis

    const int xr  = tid >> 1;
    const int xk  = (tid & 1) * 8;
    const int bpr = tid >> 5;            // B k-pair row 0..7
    const int bn0 = (tid & 31) * 4;

    float4 xreg0, xreg1, wreg0, wreg1;

    auto load_g = [&](int kb_) {
        int row = m0 + xr;
        if (row < N) {
            xreg0 = *(const float4*)&X[(size_t)row * DIN + kb_ + xk];
            xreg1 = *(const float4*)&X[(size_t)row * DIN + kb_ + xk + 4];
        } else {
            xreg0 = make_float4(0.f, 0.f, 0.f, 0.f);
            xreg1 = xreg0;
        }
        int col = n0 + bn0;
        wreg0 = *(const float4*)&W[(size_t)(kb_ + 2 * bpr) * DOUT + col];
        wreg1 = *(const float4*)&W[(size_t)(kb_ + 2 * bpr + 1) * DOUT + col];
    };

    auto store_smem = [&]() {
        uint4 hi4, lo4;
        split_pack(xreg0.x, xreg0.y, hi4.x, lo4.x);
        split_pack(xreg0.z, xreg0.w, hi4.y, lo4.y);
        split_pack(xreg1.x, xreg1.y, hi4.z, lo4.z);
        split_pack(xreg1.z, xreg1.w, hi4.w, lo4.w);
        *(uint4*)&sAhi[xr][xk >> 1] = hi4;
        *(uint4*)&sAlo[xr][xk >> 1] = lo4;
        split_pack(wreg0.x, wreg1.x, hi4.x, lo4.x);
        split_pack(wreg0.y, wreg1.y, hi4.y, lo4.y);
        split_pack(wreg0.z, wreg1.z, hi4.z, lo4.z);
        split_pack(wreg0.w, wreg1.w, hi4.w, lo4.w);
        *(uint4*)&sBhi[bpr][bn0] = hi4;
        *(uint4*)&sBlo[bpr][bn0] = lo4;
    };

    float4 d[4][4];
    #pragma unroll
    for (int i = 0; i < 4; i++)
        #pragma unroll
        for (int j = 0; j < 4; j++) d[i][j] = make_float4(0.f, 0.f, 0.f, 0.f);

    const int tg  = lane & 3;
    const int gid = lane >> 2;

    const int arow = (lane & 7) + ((lane >> 3) & 1) * 8;
    const int akp  = (lane >> 4) * 4;
    const unsigned offA = ((wm + arow) * 12 + akp) * 4;
    const unsigned addrAhi = (unsigned)__cvta_generic_to_shared(&sAhi[0][0]) + offA;
    const unsigned addrAlo = (unsigned)__cvta_generic_to_shared(&sAlo[0][0]) + offA;

    load_g(0);
    #pragma unroll 1
    for (int kb = 0; kb < DIN; kb += 16) {
        store_smem();
        __syncthreads();
        if (kb + 16 < DIN) load_g(kb + 16);

        unsigned bh[4][2], bl[4][2];
        #pragma unroll
        for (int in = 0; in < 4; in++) {
            int bc = wn + gid + in * 8;
            bh[in][0] = sBhi[tg][bc];
            bh[in][1] = sBhi[tg + 4][bc];
            bl[in][0] = sBlo[tg][bc];
            bl[in][1] = sBlo[tg + 4][bc];
        }
        #pragma unroll
        for (int im = 0; im < 4; im++) {
            unsigned ah[4], al[4];
            ldsm4(ah, addrAhi + im * 768);
            ldsm4(al, addrAlo + im * 768);
            #pragma unroll
            for (int in = 0; in < 4; in++) {
                mma_bf16(d[im][in], ah, bh[in]);
                mma_bf16(d[im][in], ah, bl[in]);
                mma_bf16(d[im][in], al, bh[in]);
            }
        }
        __syncthreads();
    }

    // --- routed epilogue (routing arithmetic compile-time strength-reduced)
    #pragma unroll
    for (int im = 0; im < 4; im++) {
        int row0 = m0 + wm + im * 16 + gid;
        #pragma unroll
        for (int in = 0; in < 4; in++) {
            int col = n0 + wn + in * 8 + tg * 2;
            float b0 = __ldg(&bias[col]);
            float b1 = __ldg(&bias[col + 1]);
            int reg = col / HC;           // col even, HC even -> pair same region
            int c   = col - reg * HC;
            #pragma unroll
            for (int half = 0; half < 2; half++) {
                int row = row0 + half * 8;
                if (row >= N) continue;
                float2 o = half ? make_float2(d[im][in].z + b0, d[im][in].w + b1)
                                : make_float2(d[im][in].x + b0, d[im][in].y + b1);
                if (reg == 0) {
                    *(float2*)&qs[(size_t)row * 2 * HC + c] = o;
                } else if (reg == 3) {
                    *(float2*)&qs[(size_t)row * 2 * HC + HC + c] = o;
                } else {
                    int h  = c / C;
                    int ch = c - h * C;
                    size_t base = ((size_t)row * H + h) * 2 * C
                                + (ch >> 2) * 8 + (ch & 3) + (reg == 2 ? 4 : 0);
                    *(__half2*)&kv[base] = __float22half2_rn(o);
                }
            }
        }
    }
}

// =====================================================================
// CSR build
// =====================================================================
__global__ void zero_cnt_kernel(int* __restrict__ cnt, int n)
{
    int i = blockIdx.x * blockDim.x + threadIdx.x;
    if (i < n) cnt[i] = 0;
}

__global__ void hist_kernel(const int* __restrict__ dst, int* __restrict__ cnt, int E)
{
    int e = blockIdx.x * blockDim.x + threadIdx.x;
    if (e < E) atomicAdd(&cnt[dst[e]], 1);
}

__global__ void scan_block_kernel(const int* __restrict__ cnt,
                                  int* __restrict__ row,
                                  int* __restrict__ bsum, int n)
{
    __shared__ int sh[512];
    int t = threadIdx.x;
    int g = blockIdx.x * 512 + t;
    int v = (g < n) ? cnt[g] : 0;
    sh[t] = v;
    __syncthreads();
    #pragma unroll
    for (int off = 1; off < 512; off <<= 1) {
        int tmp = (t >= off) ? sh[t - off] : 0;
        __syncthreads();
        sh[t] += tmp;
        __syncthreads();
    }
    if (g < n) row[g] = sh[t] - v;
    if (t == 511) bsum[blockIdx.x] = sh[511];
}

__global__ void scan_bsum_kernel(const int* __restrict__ bsum,
                                 int* __restrict__ boff, int nb)
{
    __shared__ int sh[256];
    int t = threadIdx.x;
    int v = (t < nb) ? bsum[t] : 0;
    sh[t] = v;
    __syncthreads();
    #pragma unroll
    for (int off = 1; off < 256; off <<= 1) {
        int tmp = (t >= off) ? sh[t - off] : 0;
        __syncthreads();
        sh[t] += tmp;
        __syncthreads();
    }
    boff[t] = sh[t] - v;
}

__global__ void scan_add_kernel(int* __restrict__ row, const int* __restrict__ boff,
                                int* __restrict__ cur, int n)
{
    int g = blockIdx.x * blockDim.x + threadIdx.x;
    if (g < n) {
        int r = row[g] + boff[g >> 9];
        row[g] = r;
        cur[g] = r;
    }
}

__global__ void scatter_kernel(const int* __restrict__ src, const int* __restrict__ dst,
                               int* __restrict__ cur, int* __restrict__ csrc, int E)
{
    int e = blockIdx.x * blockDim.x + threadIdx.x;
    if (e < E) {
        int p = atomicAdd(&cur[dst[e]], 1);
        csrc[p] = src[e];
    }
}

// =====================================================================
// Attention: q fp32 (qs region 0), fused fp16 kv cache, skip fp32.
// h-major warp mapping. LPE = C/4 lanes/edge, 32/LPE edges in flight.
// Depth-2 software-pipelined gather loop; exp via raw ex2.approx (MUFU)
// with log2(e)*scale folded into q; 64-thread blocks.
// =====================================================================
template <int LPE>
__global__ void attn_kernel(const float* __restrict__ qs,
                            const __half* __restrict__ kv,
                            const int* __restrict__ row,
                            const int* __restrict__ cnt,
                            const int* __restrict__ csrc,
                            float* __restrict__ dstb,
                            int H, float scale, int relu, int Nn)
{
    constexpr int EPW = 32 / LPE;
    constexpr int C   = LPE * 4;

    int w    = (blockIdx.x * blockDim.x + threadIdx.x) >> 5;
    int lane = threadIdx.x & 31;
    if (w >= Nn * H) return;
    int h = w / Nn;            // h-major
    int n = w - h * Nn;
    const int HC = H * C;
    int sl  = lane & (LPE - 1);
    int sub = lane / LPE;

    float4 q4 = *(const float4*)&qs[(size_t)n * 2 * HC + h * C + sl * 4];
    float qsc = scale * 1.44269504089f;     // exp(x) = exp2(x*log2 e)
    q4.x *= qsc; q4.y *= qsc; q4.z *= qsc; q4.w *= qsc;

    int start = row[n];
    int deg   = cnt[n];

    float  l = 0.f;
    float4 acc = make_float4(0.f, 0.f, 0.f, 0.f);

    for (int base = 0; base < deg; base += 32) {
        int nb = min(32, deg - base);
        int sp = (lane < nb) ? __ldg(&csrc[start + base + lane]) : 0;
        int ng = (nb + EPW - 1) / EPW;

        // prologue: issue load for group 0
        int s0 = __shfl_sync(0xffffffffu, sp, sub & 31);
        uint4 raw = __ldg((const uint4*)&kv[((size_t)s0 * H + h) * 2 * C + sl * 8]);

        for (int g = 0; g < ng; g++) {
            uint4 cur   = raw;
            bool  valid = (g * EPW + sub) < nb;
            if (g + 1 < ng) {   // issue next gather BEFORE computing current
                int s1 = __shfl_sync(0xffffffffu, sp, ((g + 1) * EPW + sub) & 31);
                raw = __ldg((const uint4*)&kv[((size_t)s1 * H + h) * 2 * C + sl * 8]);
            }

            float2 k01 = h2f(cur.x), k23 = h2f(cur.y);
            float2 v01 = h2f(cur.z), v23 = h2f(cur.w);

            float dot = q4.x * k01.x;
            dot = fmaf(q4.y, k01.y, dot);
            dot = fmaf(q4.z, k23.x, dot);
            dot = fmaf(q4.w, k23.y, dot);
            #pragma unroll
            for (int o = 1; o < LPE; o <<= 1)
                dot += __shfl_xor_sync(0xffffffffu, dot, o);

            float p = valid ? ex2_approx(dot) : 0.f;
            l += p;
            acc.x = fmaf(p, v01.x, acc.x);
            acc.y = fmaf(p, v01.y, acc.y);
            acc.z = fmaf(p, v23.x, acc.z);
            acc.w = fmaf(p, v23.y, acc.w);
        }
    }

    #pragma unroll
    for (int o = LPE; o < 32; o <<= 1) {
        l     += __shfl_xor_sync(0xffffffffu, l, o);
        acc.x += __shfl_xor_sync(0xffffffffu, acc.x, o);
        acc.y += __shfl_xor_sync(0xffffffffu, acc.y, o);
        acc.z += __shfl_xor_sync(0xffffffffu, acc.z, o);
        acc.w += __shfl_xor_sync(0xffffffffu, acc.w, o);
    }

    float inv = 1.0f / (l + 1e-16f);
    if (lane < LPE) {
        float4 o4 = *(const float4*)&qs[(size_t)n * 2 * HC + HC + h * C + lane * 4];
        o4.x += acc.x * inv;
        o4.y += acc.y * inv;
        o4.z += acc.z * inv;
        o4.w += acc.w * inv;
        if (relu) {
            o4.x = fmaxf(o4.x, 0.f);
            o4.y = fmaxf(o4.y, 0.f);
            o4.z = fmaxf(o4.z, 0.f);
            o4.w = fmaxf(o4.w, 0.f);
        }
        *(float4*)&dstb[(size_t)n * HC + h * C + lane * 4] = o4;
    }
}

// =====================================================================
// Host-side orchestration
// =====================================================================
static void* sym_addr(const void* symbol)
{
    void* p = nullptr;
    cudaGetSymbolAddress(&p, symbol);
    return p;
}

static void launch_attn(const float* qs, const __half* kv,
                        const int* row, const int* cnt, const int* csrc,
                        float* dstb, int N, int H, int C, bool relu)
{
    int NH = N * H;
    int blocks = (NH * 32 + 63) / 64;       // 64-thread blocks (2 warps)
    float scale = 1.0f / sqrtf((float)C);
    if (C == 32)
        attn_kernel<8><<<blocks, 64>>>(qs, kv, row, cnt, csrc, dstb, H, scale, relu ? 1 : 0, N);
    else
        attn_kernel<16><<<blocks, 64>>>(qs, kv, row, cnt, csrc, dstb, H, scale, relu ? 1 : 0, N);
}

extern "C" void kernel_launch(void* const* d_in, const int* in_sizes, int n_in,
                              void* d_out, int out_size)
{
    const float* x  = (const float*)d_in[0];
    const int*   ei = (const int*)d_in[1];
    const int N = in_sizes[0] / 64;
    const int E = in_sizes[1] / 2;
    const int* src = ei;
    const int* dst = ei + E;

    const float* W[24];
    for (int i = 0; i < 24; i++) W[i] = (const float*)d_in[2 + i];

    float*  qs  = (float*)sym_addr(g_qs);
    __half* kv  = (__half*)sym_addr(g_kv);
    float* h1   = (float*)sym_addr(g_h1);
    float* h2   = (float*)sym_addr(g_h2);
    float* wp   = (float*)sym_addr(g_wp);
    float* bp   = (float*)sym_addr(g_bp);
    int*   cnt  = (int*)sym_addr(g_cnt);
    int*   row  = (int*)sym_addr(g_row);
    int*   cur  = (int*)sym_addr(g_cur);
    int*   bsum = (int*)sym_addr(g_bsum);
    int*   boff = (int*)sym_addr(g_boff);
    int*   csrc = (int*)sym_addr(g_csrc);
    float* out  = (float*)d_out;

    float* wp1 = wp;            float* bp1 = bp;
    float* wp2 = wp + 57344;    float* bp2 = bp + 896;
    float* wp3 = wp + 172032;   float* bp3 = bp + 1408;

    int nscan = (N + 511) / 512;

    // launch order keeps layer-1 GEMM in the ncu capture slot (#4)
    pack_w<<<(64 * 896 + 255) / 256, 256>>>(W[0], W[2], W[4], W[6], W[1], W[3], W[5], W[7],
                                            wp1, bp1, 64, 224);
    zero_cnt_kernel<<<(N + 255) / 256, 256>>>(cnt, N);
    hist_kernel<<<(E + 255) / 256, 256>>>(dst, cnt, E);

    // Layer 1 fused GEMM: [N,64] x [64,896]   (launch #4)
    // n-blocks on x (fast axis) -> X tile reused across n, read from DRAM once
    {
        dim3 grid(896 / 128, (N + 127) / 128);
        gemm_bf16s<64, 224, 32><<<grid, 256>>>(x, wp1, bp1, qs, kv, N);
    }

    scan_block_kernel<<<nscan, 512>>>(cnt, row, bsum, N);
    scan_bsum_kernel<<<1, 256>>>(bsum, boff, nscan);
    scan_add_kernel<<<(N + 255) / 256, 256>>>(row, boff, cur, N);
    scatter_kernel<<<(E + 255) / 256, 256>>>(src, dst, cur, csrc, E);
    pack_w<<<(224 * 512 + 255) / 256, 256>>>(W[8], W[10], W[12], W[14], W[9], W[11], W[13], W[15],
                                             wp2, bp2, 224, 128);
    pack_w<<<(128 * 256 + 255) / 256, 256>>>(W[16], W[18], W[20], W[22], W[17], W[19], W[21], W[23],
                                             wp3, bp3, 128, 64);

    // Layer 1 attn: H=7, C=32, relu -> h1
    launch_attn(qs, kv, row, cnt, csrc, h1, N, 7, 32, true);

    // Layer 2: [N,224] x [224,512]
    {
        dim3 grid(512 / 128, (N + 127) / 128);
        gemm_bf16s<224, 128, 32><<<grid, 256>>>(h1, wp2, bp2, qs, kv, N);
    }
    launch_attn(qs, kv, row, cnt, csrc, h2, N, 4, 32, true);

    // Layer 3: [N,128] x [128,256]
    {
        dim3 grid(256 / 128, (N + 127) / 128);
        gemm_bf16s<128, 64, 64><<<grid, 256>>>(h2, wp3, bp3, qs, kv, N);
    }
    launch_attn(qs, kv, row, cnt, csrc, out, N, 1, 64, false);
}

// round 16
// speedup vs baseline: 1.3525x; 1.0153x over previous
#include <cuda_runtime.h>
#include <cuda_bf16.h>
#include <cuda_fp16.h>
#include <math.h>

#define NN 100000
#define EE 800000

// ---------------- scratch (device globals; no allocations) ----------------
__device__ float  g_qs[NN * 448];           // fp32 q|skip  [N, 2*HC]
__device__ __half g_kv[NN * 448];           // fp16 fused kv [N*H, 2*C] chunked
__device__ float  g_h1[NN * 224];
__device__ float  g_h2[NN * 128];
__device__ float  g_wp[204800];             // packed weights, 3 layers
__device__ float  g_bp[1664];               // packed biases
// CSR scratch
__device__ int g_cnt[NN];
__device__ int g_row[NN + 1];
__device__ int g_cur[NN];
__device__ int g_bsum[256];
__device__ int g_boff[256];
__device__ int g_csrc[EE];

// ---------------- helpers ---------------------------------------------------
__device__ __forceinline__ void split_pack(float a, float b, unsigned& hi, unsigned& lo)
{
    __nv_bfloat16 ha = __float2bfloat16(a);
    __nv_bfloat16 hb = __float2bfloat16(b);
    __nv_bfloat16 la = __float2bfloat16(a - __bfloat162float(ha));
    __nv_bfloat16 lb = __float2bfloat16(b - __bfloat162float(hb));
    __nv_bfloat162 h2 = __halves2bfloat162(ha, hb);
    __nv_bfloat162 l2 = __halves2bfloat162(la, lb);
    hi = *(unsigned*)&h2;
    lo = *(unsigned*)&l2;
}

__device__ __forceinline__ void mma_bf16(float4& d, const unsigned a[4], const unsigned b[2])
{
    asm volatile("mma.sync.aligned.m16n8k16.row.col.f32.bf16.bf16.f32 "
                 "{%0,%1,%2,%3}, {%4,%5,%6,%7}, {%8,%9}, {%0,%1,%2,%3};"
                 : "+f"(d.x), "+f"(d.y), "+f"(d.z), "+f"(d.w)
                 : "r"(a[0]), "r"(a[1]), "r"(a[2]), "r"(a[3]),
                   "r"(b[0]), "r"(b[1]));
}

__device__ __forceinline__ void ldsm4(unsigned a[4], unsigned addr)
{
    asm volatile("ldmatrix.sync.aligned.m8n8.x4.shared.b16 {%0,%1,%2,%3}, [%4];"
                 : "=r"(a[0]), "=r"(a[1]), "=r"(a[2]), "=r"(a[3]) : "r"(addr));
}

__device__ __forceinline__ float2 h2f(unsigned u)
{
    return __half22float2(*reinterpret_cast<__half2*>(&u));
}

__device__ __forceinline__ float ex2_approx(float x)
{
    float r;
    asm("ex2.approx.ftz.f32 %0, %1;" : "=f"(r) : "f"(x));
    return r;
}

// =====================================================================
// Weight pack: Wp[kk][j*HC + c] = Wj[kk][c]; bp[j*HC + c] = bj[c]
// =====================================================================
__global__ void pack_w(const float* __restrict__ Wq, const float* __restrict__ Wk,
                       const float* __restrict__ Wv, const float* __restrict__ Ws,
                       const float* __restrict__ bq, const float* __restrict__ bk,
                       const float* __restrict__ bv, const float* __restrict__ bs,
                       float* __restrict__ Wp, float* __restrict__ bp,
                       int din, int HC)
{
    int i = blockIdx.x * blockDim.x + threadIdx.x;
    int tot = din * 4 * HC;
    if (i < tot) {
        int kk  = i / (4 * HC);
        int rem = i - kk * 4 * HC;
        int j   = rem / HC;
        int c   = rem - j * HC;
        const float* Wj = (j == 0) ? Wq : (j == 1) ? Wk : (j == 2) ? Wv : Ws;
        Wp[i] = Wj[kk * HC + c];
    }
    if (i < 4 * HC) {
        int j = i / HC, c = i - j * HC;
        const float* bj = (j == 0) ? bq : (j == 1) ? bk : (j == 2) ? bv : bs;
        bp[i] = bj[c];
    }
}

// =====================================================================
// GEMM: X[N,DIN] @ Wp[DIN, 4*HC] + bp, routed epilogue:
//   region 0 (q) -> qs fp32 | 1 (k) -> kv fp16 | 2 (v) -> kv fp16 | 3 (s) -> qs
// kv layout: [(row*H + h)*2C] in 16B chunks {k[4j..4j+3], v[4j..4j+3]}.
// bf16 3-term split, BM=128, BN=128, BK=16, warp tile 64x32, ldmatrix A.
// GRID: blockIdx.x = n-block (fast) -> X read from DRAM once.
// =====================================================================
template <int DIN, int HC, int C>
__global__ void __launch_bounds__(256, 2)
gemm_bf16s(const float* __restrict__ X, const float* __restrict__ W,
           const float* __restrict__ bias,
           float* __restrict__ qs, __half* __restrict__ kv,
           int N)
{
    constexpr int BN   = 128;
    constexpr int BSTR = BN + 8;
    constexpr int DOUT = 4 * HC;
    constexpr int H    = HC / C;

    __shared__ unsigned sAhi[128][12];
    __shared__ unsigned sAlo[128][12];
    __shared__ unsigned sBhi[8][BSTR];
    __shared__ unsigned sBlo[8][BSTR];

    const int tid  = threadIdx.x;
    const int lane = tid & 31;
    const int warp = tid >> 5;
    const int wm   = (warp & 1) * 64;
    const int wn   = (warp >> 1) * 32;
    const int m0   = blockIdx.y * 128;    // m on the SLOW axis
    const int n0   = blockIdx.x * BN;     // n on the FAST axis

    const int xr  = tid >> 1;
    const int xk  = (tid & 1) * 8;
    const int bpr = tid >> 5;            // B k-pair row 0..7
    const int bn0 = (tid & 31) * 4;

    float4 xreg0, xreg1, wreg0, wreg1;

    auto load_g = [&](int kb_) {
        int row = m0 + xr;
        if (row < N) {
            xreg0 = *(const float4*)&X[(size_t)row * DIN + kb_ + xk];
            xreg1 = *(const float4*)&X[(size_t)row * DIN + kb_ + xk + 4];
        } else {
            xreg0 = make_float4(0.f, 0.f, 0.f, 0.f);
            xreg1 = xreg0;
        }
        int col = n0 + bn0;
        wreg0 = *(const float4*)&W[(size_t)(kb_ + 2 * bpr) * DOUT + col];
        wreg1 = *(const float4*)&W[(size_t)(kb_ + 2 * bpr + 1) * DOUT + col];
    };

    auto store_smem = [&]() {
        uint4 hi4, lo4;
        split_pack(xreg0.x, xreg0.y, hi4.x, lo4.x);
        split_pack(xreg0.z, xreg0.w, hi4.y, lo4.y);
        split_pack(xreg1.x, xreg1.y, hi4.z, lo4.z);
        split_pack(xreg1.z, xreg1.w, hi4.w, lo4.w);
        *(uint4*)&sAhi[xr][xk >> 1] = hi4;
        *(uint4*)&sAlo[xr][xk >> 1] = lo4;
        split_pack(wreg0.x, wreg1.x, hi4.x, lo4.x);
        split_pack(wreg0.y, wreg1.y, hi4.y, lo4.y);
        split_pack(wreg0.z, wreg1.z, hi4.z, lo4.z);
        split_pack(wreg0.w, wreg1.w, hi4.w, lo4.w);
        *(uint4*)&sBhi[bpr][bn0] = hi4;
        *(uint4*)&sBlo[bpr][bn0] = lo4;
    };

    float4 d[4][4];
    #pragma unroll
    for (int i = 0; i < 4; i++)
        #pragma unroll
        for (int j = 0; j < 4; j++) d[i][j] = make_float4(0.f, 0.f, 0.f, 0.f);

    const int tg  = lane & 3;
    const int gid = lane >> 2;

    const int arow = (lane & 7) + ((lane >> 3) & 1) * 8;
    const int akp  = (lane >> 4) * 4;
    const unsigned offA = ((wm + arow) * 12 + akp) * 4;
    const unsigned addrAhi = (unsigned)__cvta_generic_to_shared(&sAhi[0][0]) + offA;
    const unsigned addrAlo = (unsigned)__cvta_generic_to_shared(&sAlo[0][0]) + offA;

    load_g(0);
    #pragma unroll 1
    for (int kb = 0; kb < DIN; kb += 16) {
        store_smem();
        __syncthreads();
        if (kb + 16 < DIN) load_g(kb + 16);

        unsigned bh[4][2], bl[4][2];
        #pragma unroll
        for (int in = 0; in < 4; in++) {
            int bc = wn + gid + in * 8;
            bh[in][0] = sBhi[tg][bc];
            bh[in][1] = sBhi[tg + 4][bc];
            bl[in][0] = sBlo[tg][bc];
            bl[in][1] = sBlo[tg + 4][bc];
        }
        #pragma unroll
        for (int im = 0; im < 4; im++) {
            unsigned ah[4], al[4];
            ldsm4(ah, addrAhi + im * 768);
            ldsm4(al, addrAlo + im * 768);
            #pragma unroll
            for (int in = 0; in < 4; in++) {
                mma_bf16(d[im][in], ah, bh[in]);
                mma_bf16(d[im][in], ah, bl[in]);
                mma_bf16(d[im][in], al, bh[in]);
            }
        }
        __syncthreads();
    }

    // --- routed epilogue (routing arithmetic compile-time strength-reduced)
    #pragma unroll
    for (int im = 0; im < 4; im++) {
        int row0 = m0 + wm + im * 16 + gid;
        #pragma unroll
        for (int in = 0; in < 4; in++) {
            int col = n0 + wn + in * 8 + tg * 2;
            float b0 = __ldg(&bias[col]);
            float b1 = __ldg(&bias[col + 1]);
            int reg = col / HC;           // col even, HC even -> pair same region
            int c   = col - reg * HC;
            #pragma unroll
            for (int half = 0; half < 2; half++) {
                int row = row0 + half * 8;
                if (row >= N) continue;
                float2 o = half ? make_float2(d[im][in].z + b0, d[im][in].w + b1)
                                : make_float2(d[im][in].x + b0, d[im][in].y + b1);
                if (reg == 0) {
                    *(float2*)&qs[(size_t)row * 2 * HC + c] = o;
                } else if (reg == 3) {
                    *(float2*)&qs[(size_t)row * 2 * HC + HC + c] = o;
                } else {
                    int h  = c / C;
                    int ch = c - h * C;
                    size_t base = ((size_t)row * H + h) * 2 * C
                                + (ch >> 2) * 8 + (ch & 3) + (reg == 2 ? 4 : 0);
                    *(__half2*)&kv[base] = __float22half2_rn(o);
                }
            }
        }
    }
}

// =====================================================================
// CSR build
// =====================================================================
__global__ void zero_cnt_kernel(int* __restrict__ cnt, int n)
{
    int i = blockIdx.x * blockDim.x + threadIdx.x;
    if (i < n) cnt[i] = 0;
}

__global__ void hist_kernel(const int* __restrict__ dst, int* __restrict__ cnt, int E)
{
    int e = blockIdx.x * blockDim.x + threadIdx.x;
    if (e < E) atomicAdd(&cnt[dst[e]], 1);
}

__global__ void scan_block_kernel(const int* __restrict__ cnt,
                                  int* __restrict__ row,
                                  int* __restrict__ bsum, int n)
{
    __shared__ int sh[512];
    int t = threadIdx.x;
    int g = blockIdx.x * 512 + t;
    int v = (g < n) ? cnt[g] : 0;
    sh[t] = v;
    __syncthreads();
    #pragma unroll
    for (int off = 1; off < 512; off <<= 1) {
        int tmp = (t >= off) ? sh[t - off] : 0;
        __syncthreads();
        sh[t] += tmp;
        __syncthreads();
    }
    if (g < n) row[g] = sh[t] - v;
    if (t == 511) bsum[blockIdx.x] = sh[511];
}

__global__ void scan_bsum_kernel(const int* __restrict__ bsum,
                                 int* __restrict__ boff, int nb)
{
    __shared__ int sh[256];
    int t = threadIdx.x;
    int v = (t < nb) ? bsum[t] : 0;
    sh[t] = v;
    __syncthreads();
    #pragma unroll
    for (int off = 1; off < 256; off <<= 1) {
        int tmp = (t >= off) ? sh[t - off] : 0;
        __syncthreads();
        sh[t] += tmp;
        __syncthreads();
    }
    boff[t] = sh[t] - v;
}

__global__ void scan_add_kernel(int* __restrict__ row, const int* __restrict__ boff,
                                int* __restrict__ cur, int n)
{
    int g = blockIdx.x * blockDim.x + threadIdx.x;
    if (g < n) {
        int r = row[g] + boff[g >> 9];
        row[g] = r;
        cur[g] = r;
    }
}

__global__ void scatter_kernel(const int* __restrict__ src, const int* __restrict__ dst,
                               int* __restrict__ cur, int* __restrict__ csrc, int E)
{
    int e = blockIdx.x * blockDim.x + threadIdx.x;
    if (e < E) {
        int p = atomicAdd(&cur[dst[e]], 1);
        csrc[p] = src[e];
    }
}

// =====================================================================
// Attention: q fp32 (qs region 0), fused fp16 kv cache, skip fp32.
// h-major warp mapping. LPE = C/4 lanes/edge, 32/LPE edges in flight.
// DIRECT-INDEXED group loop: each LPE-lane group walks edges
// e = sub, sub+EPW, ... reading indices straight from csrc (broadcast
// LDG) with distance-2 index prefetch feeding a depth-2 kv prefetch.
// No outer 32-blocking, no index shuffles, no valid predicates.
// Dot-reduce uses group-local shuffle masks (trip counts diverge
// between groups). exp via raw ex2.approx; 64-thread blocks.
// =====================================================================
template <int LPE>
__global__ void attn_kernel(const float* __restrict__ qs,
                            const __half* __restrict__ kv,
                            const int* __restrict__ row,
                            const int* __restrict__ cnt,
                            const int* __restrict__ csrc,
                            float* __restrict__ dstb,
                            int H, float scale, int relu, int Nn)
{
    constexpr int EPW = 32 / LPE;
    constexpr int C   = LPE * 4;

    int w    = (blockIdx.x * blockDim.x + threadIdx.x) >> 5;
    int lane = threadIdx.x & 31;
    if (w >= Nn * H) return;
    int h = w / Nn;            // h-major
    int n = w - h * Nn;
    const int HC = H * C;
    int sl  = lane & (LPE - 1);
    int sub = lane / LPE;
    const unsigned gmask = (((LPE < 32) ? ((1u << LPE) - 1u) : 0xffffffffu)) << (sub * LPE);

    float4 q4 = *(const float4*)&qs[(size_t)n * 2 * HC + h * C + sl * 4];
    float qsc = scale * 1.44269504089f;     // exp(x) = exp2(x*log2 e)
    q4.x *= qsc; q4.y *= qsc; q4.z *= qsc; q4.w *= qsc;

    int start = row[n];
    int deg   = cnt[n];
    const int* ep = csrc + start;

    float  l = 0.f;
    float4 acc = make_float4(0.f, 0.f, 0.f, 0.f);

    // prologue: group 'sub' handles edges sub, sub+EPW, ...
    uint4 raw = make_uint4(0u, 0u, 0u, 0u);
    int   s_nxt = 0;
    if (sub < deg) {
        int s0 = __ldg(&ep[sub]);
        raw = __ldg((const uint4*)&kv[((size_t)s0 * H + h) * 2 * C + sl * 8]);
        if (sub + EPW < deg) s_nxt = __ldg(&ep[sub + EPW]);
    }

    for (int e = sub; e < deg; e += EPW) {
        uint4 cur = raw;
        if (e + EPW < deg) {
            raw = __ldg((const uint4*)&kv[((size_t)s_nxt * H + h) * 2 * C + sl * 8]);
            if (e + 2 * EPW < deg) s_nxt = __ldg(&ep[e + 2 * EPW]);
        }

        float2 k01 = h2f(cur.x), k23 = h2f(cur.y);
        float2 v01 = h2f(cur.z), v23 = h2f(cur.w);

        float dot = q4.x * k01.x;
        dot = fmaf(q4.y, k01.y, dot);
        dot = fmaf(q4.z, k23.x, dot);
        dot = fmaf(q4.w, k23.y, dot);
        #pragma unroll
        for (int o = 1; o < LPE; o <<= 1)
            dot += __shfl_xor_sync(gmask, dot, o);

        float p = ex2_approx(dot);
        l += p;
        acc.x = fmaf(p, v01.x, acc.x);
        acc.y = fmaf(p, v01.y, acc.y);
        acc.z = fmaf(p, v23.x, acc.z);
        acc.w = fmaf(p, v23.y, acc.w);
    }

    // combine across edge-slot groups (all lanes reconverged here)
    #pragma unroll
    for (int o = LPE; o < 32; o <<= 1) {
        l     += __shfl_xor_sync(0xffffffffu, l, o);
        acc.x += __shfl_xor_sync(0xffffffffu, acc.x, o);
        acc.y += __shfl_xor_sync(0xffffffffu, acc.y, o);
        acc.z += __shfl_xor_sync(0xffffffffu, acc.z, o);
        acc.w += __shfl_xor_sync(0xffffffffu, acc.w, o);
    }

    float inv = 1.0f / (l + 1e-16f);
    if (lane < LPE) {
        float4 o4 = *(const float4*)&qs[(size_t)n * 2 * HC + HC + h * C + lane * 4];
        o4.x += acc.x * inv;
        o4.y += acc.y * inv;
        o4.z += acc.z * inv;
        o4.w += acc.w * inv;
        if (relu) {
            o4.x = fmaxf(o4.x, 0.f);
            o4.y = fmaxf(o4.y, 0.f);
            o4.z = fmaxf(o4.z, 0.f);
            o4.w = fmaxf(o4.w, 0.f);
        }
        *(float4*)&dstb[(size_t)n * HC + h * C + lane * 4] = o4;
    }
}

// =====================================================================
// Host-side orchestration
// =====================================================================
static void* sym_addr(const void* symbol)
{
    void* p = nullptr;
    cudaGetSymbolAddress(&p, symbol);
    return p;
}

static void launch_attn(const float* qs, const __half* kv,
                        const int* row, const int* cnt, const int* csrc,
                        float* dstb, int N, int H, int C, bool relu)
{
    int NH = N * H;
    int blocks = (NH * 32 + 63) / 64;       // 64-thread blocks (2 warps)
    float scale = 1.0f / sqrtf((float)C);
    if (C == 32)
        attn_kernel<8><<<blocks, 64>>>(qs, kv, row, cnt, csrc, dstb, H, scale, relu ? 1 : 0, N);
    else
        attn_kernel<16><<<blocks, 64>>>(qs, kv, row, cnt, csrc, dstb, H, scale, relu ? 1 : 0, N);
}

extern "C" void kernel_launch(void* const* d_in, const int* in_sizes, int n_in,
                              void* d_out, int out_size)
{
    const float* x  = (const float*)d_in[0];
    const int*   ei = (const int*)d_in[1];
    const int N = in_sizes[0] / 64;
    const int E = in_sizes[1] / 2;
    const int* src = ei;
    const int* dst = ei + E;

    const float* W[24];
    for (int i = 0; i < 24; i++) W[i] = (const float*)d_in[2 + i];

    float*  qs  = (float*)sym_addr(g_qs);
    __half* kv  = (__half*)sym_addr(g_kv);
    float* h1   = (float*)sym_addr(g_h1);
    float* h2   = (float*)sym_addr(g_h2);
    float* wp   = (float*)sym_addr(g_wp);
    float* bp   = (float*)sym_addr(g_bp);
    int*   cnt  = (int*)sym_addr(g_cnt);
    int*   row  = (int*)sym_addr(g_row);
    int*   cur  = (int*)sym_addr(g_cur);
    int*   bsum = (int*)sym_addr(g_bsum);
    int*   boff = (int*)sym_addr(g_boff);
    int*   csrc = (int*)sym_addr(g_csrc);
    float* out  = (float*)d_out;

    float* wp1 = wp;            float* bp1 = bp;
    float* wp2 = wp + 57344;    float* bp2 = bp + 896;
    float* wp3 = wp + 172032;   float* bp3 = bp + 1408;

    int nscan = (N + 511) / 512;

    // launch order keeps layer-1 GEMM in the ncu capture slot (#4)
    pack_w<<<(64 * 896 + 255) / 256, 256>>>(W[0], W[2], W[4], W[6], W[1], W[3], W[5], W[7],
                                            wp1, bp1, 64, 224);
    zero_cnt_kernel<<<(N + 255) / 256, 256>>>(cnt, N);
    hist_kernel<<<(E + 255) / 256, 256>>>(dst, cnt, E);

    // Layer 1 fused GEMM: [N,64] x [64,896]   (launch #4)
    {
        dim3 grid(896 / 128, (N + 127) / 128);
        gemm_bf16s<64, 224, 32><<<grid, 256>>>(x, wp1, bp1, qs, kv, N);
    }

    scan_block_kernel<<<nscan, 512>>>(cnt, row, bsum, N);
    scan_bsum_kernel<<<1, 256>>>(bsum, boff, nscan);
    scan_add_kernel<<<(N + 255) / 256, 256>>>(row, boff, cur, N);
    scatter_kernel<<<(E + 255) / 256, 256>>>(src, dst, cur, csrc, E);
    pack_w<<<(224 * 512 + 255) / 256, 256>>>(W[8], W[10], W[12], W[14], W[9], W[11], W[13], W[15],
                                             wp2, bp2, 224, 128);
    pack_w<<<(128 * 256 + 255) / 256, 256>>>(W[16], W[18], W[20], W[22], W[17], W[19], W[21], W[23],
                                             wp3, bp3, 128, 64);

    // Layer 1 attn: H=7, C=32, relu -> h1
    launch_attn(qs, kv, row, cnt, csrc, h1, N, 7, 32, true);

    // Layer 2: [N,224] x [224,512]
    {
        dim3 grid(512 / 128, (N + 127) / 128);
        gemm_bf16s<224, 128, 32><<<grid, 256>>>(h1, wp2, bp2, qs, kv, N);
    }
    launch_attn(qs, kv, row, cnt, csrc, h2, N, 4, 32, true);

    // Layer 3: [N,128] x [128,256]
    {
        dim3 grid(256 / 128, (N + 127) / 128);
        gemm_bf16s<128, 64, 64><<<grid, 256>>>(h2, wp3, bp3, qs, kv, N);
    }
    launch_attn(qs, kv, row, cnt, csrc, out, N, 1, 64, false);
}

// round 17
// speedup vs baseline: 1.8186x; 1.3446x over previous
#include <cuda_runtime.h>
#include <cuda_bf16.h>
#include <cuda_fp16.h>
#include <math.h>

#define NN 100000
#define EE 800000

// ---------------- scratch (device globals; no allocations) ----------------
__device__ float  g_qs[NN * 448];           // fp32 q|skip  [N, 2*HC]
__device__ __half g_kv[NN * 448];           // fp16 fused kv [N, H*2C] chunked
__device__ float  g_h1[NN * 224];
__device__ float  g_h2[NN * 128];
__device__ float  g_wp[204800];             // packed weights, 3 layers
__device__ float  g_bp[1664];               // packed biases
// CSR scratch
__device__ int g_cnt[NN];
__device__ int g_row[NN + 1];
__device__ int g_cur[NN];
__device__ int g_bsum[256];
__device__ int g_boff[256];
__device__ int g_csrc[EE];

// ---------------- helpers ---------------------------------------------------
__device__ __forceinline__ void split_pack(float a, float b, unsigned& hi, unsigned& lo)
{
    __nv_bfloat16 ha = __float2bfloat16(a);
    __nv_bfloat16 hb = __float2bfloat16(b);
    __nv_bfloat16 la = __float2bfloat16(a - __bfloat162float(ha));
    __nv_bfloat16 lb = __float2bfloat16(b - __bfloat162float(hb));
    __nv_bfloat162 h2 = __halves2bfloat162(ha, hb);
    __nv_bfloat162 l2 = __halves2bfloat162(la, lb);
    hi = *(unsigned*)&h2;
    lo = *(unsigned*)&l2;
}

__device__ __forceinline__ void mma_bf16(float4& d, const unsigned a[4], const unsigned b[2])
{
    asm volatile("mma.sync.aligned.m16n8k16.row.col.f32.bf16.bf16.f32 "
                 "{%0,%1,%2,%3}, {%4,%5,%6,%7}, {%8,%9}, {%0,%1,%2,%3};"
                 : "+f"(d.x), "+f"(d.y), "+f"(d.z), "+f"(d.w)
                 : "r"(a[0]), "r"(a[1]), "r"(a[2]), "r"(a[3]),
                   "r"(b[0]), "r"(b[1]));
}

__device__ __forceinline__ void ldsm4(unsigned a[4], unsigned addr)
{
    asm volatile("ldmatrix.sync.aligned.m8n8.x4.shared.b16 {%0,%1,%2,%3}, [%4];"
                 : "=r"(a[0]), "=r"(a[1]), "=r"(a[2]), "=r"(a[3]) : "r"(addr));
}

__device__ __forceinline__ float2 h2f(unsigned u)
{
    return __half22float2(*reinterpret_cast<__half2*>(&u));
}

__device__ __forceinline__ float ex2_approx(float x)
{
    float r;
    asm("ex2.approx.ftz.f32 %0, %1;" : "=f"(r) : "f"(x));
    return r;
}

// =====================================================================
// Weight pack: Wp[kk][j*HC + c] = Wj[kk][c]; bp[j*HC + c] = bj[c]
// =====================================================================
__global__ void pack_w(const float* __restrict__ Wq, const float* __restrict__ Wk,
                       const float* __restrict__ Wv, const float* __restrict__ Ws,
                       const float* __restrict__ bq, const float* __restrict__ bk,
                       const float* __restrict__ bv, const float* __restrict__ bs,
                       float* __restrict__ Wp, float* __restrict__ bp,
                       int din, int HC)
{
    int i = blockIdx.x * blockDim.x + threadIdx.x;
    int tot = din * 4 * HC;
    if (i < tot) {
        int kk  = i / (4 * HC);
        int rem = i - kk * 4 * HC;
        int j   = rem / HC;
        int c   = rem - j * HC;
        const float* Wj = (j == 0) ? Wq : (j == 1) ? Wk : (j == 2) ? Wv : Ws;
        Wp[i] = Wj[kk * HC + c];
    }
    if (i < 4 * HC) {
        int j = i / HC, c = i - j * HC;
        const float* bj = (j == 0) ? bq : (j == 1) ? bk : (j == 2) ? bv : bs;
        bp[i] = bj[c];
    }
}

// =====================================================================
// GEMM: X[N,DIN] @ Wp[DIN, 4*HC] + bp, routed epilogue:
//   region 0 (q) -> qs fp32 | 1 (k) -> kv fp16 | 2 (v) -> kv fp16 | 3 (s) -> qs
// kv layout: [(row*H + h)*2C] in 16B chunks {k[4j..4j+3], v[4j..4j+3]}.
// bf16 3-term split, BM=128, BN=128, BK=16, warp tile 64x32, ldmatrix A.
// GRID: blockIdx.x = n-block (fast) -> X read from DRAM once.
// =====================================================================
template <int DIN, int HC, int C>
__global__ void __launch_bounds__(256, 2)
gemm_bf16s(const float* __restrict__ X, const float* __restrict__ W,
           const float* __restrict__ bias,
           float* __restrict__ qs, __half* __restrict__ kv,
           int N)
{
    constexpr int BN   = 128;
    constexpr int BSTR = BN + 8;
    constexpr int DOUT = 4 * HC;
    constexpr int H    = HC / C;

    __shared__ unsigned sAhi[128][12];
    __shared__ unsigned sAlo[128][12];
    __shared__ unsigned sBhi[8][BSTR];
    __shared__ unsigned sBlo[8][BSTR];

    const int tid  = threadIdx.x;
    const int lane = tid & 31;
    const int warp = tid >> 5;
    const int wm   = (warp & 1) * 64;
    const int wn   = (warp >> 1) * 32;
    const int m0   = blockIdx.y * 128;    // m on the SLOW axis
    const int n0   = blockIdx.x * BN;     // n on the FAST axis

    const int xr  = tid >> 1;
    const int xk  = (tid & 1) * 8;
    const int bpr = tid >> 5;            // B k-pair row 0..7
    const int bn0 = (tid & 31) * 4;

    float4 xreg0, xreg1, wreg0, wreg1;

    auto load_g = [&](int kb_) {
        int row = m0 + xr;
        if (row < N) {
            xreg0 = *(const float4*)&X[(size_t)row * DIN + kb_ + xk];
            xreg1 = *(const float4*)&X[(size_t)row * DIN + kb_ + xk + 4];
        } else {
            xreg0 = make_float4(0.f, 0.f, 0.f, 0.f);
            xreg1 = xreg0;
        }
        int col = n0 + bn0;
        wreg0 = *(const float4*)&W[(size_t)(kb_ + 2 * bpr) * DOUT + col];
        wreg1 = *(const float4*)&W[(size_t)(kb_ + 2 * bpr + 1) * DOUT + col];
    };

    auto store_smem = [&]() {
        uint4 hi4, lo4;
        split_pack(xreg0.x, xreg0.y, hi4.x, lo4.x);
        split_pack(xreg0.z, xreg0.w, hi4.y, lo4.y);
        split_pack(xreg1.x, xreg1.y, hi4.z, lo4.z);
        split_pack(xreg1.z, xreg1.w, hi4.w, lo4.w);
        *(uint4*)&sAhi[xr][xk >> 1] = hi4;
        *(uint4*)&sAlo[xr][xk >> 1] = lo4;
        split_pack(wreg0.x, wreg1.x, hi4.x, lo4.x);
        split_pack(wreg0.y, wreg1.y, hi4.y, lo4.y);
        split_pack(wreg0.z, wreg1.z, hi4.z, lo4.z);
        split_pack(wreg0.w, wreg1.w, hi4.w, lo4.w);
        *(uint4*)&sBhi[bpr][bn0] = hi4;
        *(uint4*)&sBlo[bpr][bn0] = lo4;
    };

    float4 d[4][4];
    #pragma unroll
    for (int i = 0; i < 4; i++)
        #pragma unroll
        for (int j = 0; j < 4; j++) d[i][j] = make_float4(0.f, 0.f, 0.f, 0.f);

    const int tg  = lane & 3;
    const int gid = lane >> 2;

    const int arow = (lane & 7) + ((lane >> 3) & 1) * 8;
    const int akp  = (lane >> 4) * 4;
    const unsigned offA = ((wm + arow) * 12 + akp) * 4;
    const unsigned addrAhi = (unsigned)__cvta_generic_to_shared(&sAhi[0][0]) + offA;
    const unsigned addrAlo = (unsigned)__cvta_generic_to_shared(&sAlo[0][0]) + offA;

    load_g(0);
    #pragma unroll 1
    for (int kb = 0; kb < DIN; kb += 16) {
        store_smem();
        __syncthreads();
        if (kb + 16 < DIN) load_g(kb + 16);

        unsigned bh[4][2], bl[4][2];
        #pragma unroll
        for (int in = 0; in < 4; in++) {
            int bc = wn + gid + in * 8;
            bh[in][0] = sBhi[tg][bc];
            bh[in][1] = sBhi[tg + 4][bc];
            bl[in][0] = sBlo[tg][bc];
            bl[in][1] = sBlo[tg + 4][bc];
        }
        #pragma unroll
        for (int im = 0; im < 4; im++) {
            unsigned ah[4], al[4];
            ldsm4(ah, addrAhi + im * 768);
            ldsm4(al, addrAlo + im * 768);
            #pragma unroll
            for (int in = 0; in < 4; in++) {
                mma_bf16(d[im][in], ah, bh[in]);
                mma_bf16(d[im][in], ah, bl[in]);
                mma_bf16(d[im][in], al, bh[in]);
            }
        }
        __syncthreads();
    }

    // --- routed epilogue (routing arithmetic compile-time strength-reduced)
    #pragma unroll
    for (int im = 0; im < 4; im++) {
        int row0 = m0 + wm + im * 16 + gid;
        #pragma unroll
        for (int in = 0; in < 4; in++) {
            int col = n0 + wn + in * 8 + tg * 2;
            float b0 = __ldg(&bias[col]);
            float b1 = __ldg(&bias[col + 1]);
            int reg = col / HC;           // col even, HC even -> pair same region
            int c   = col - reg * HC;
            #pragma unroll
            for (int half = 0; half < 2; half++) {
                int row = row0 + half * 8;
                if (row >= N) continue;
                float2 o = half ? make_float2(d[im][in].z + b0, d[im][in].w + b1)
                                : make_float2(d[im][in].x + b0, d[im][in].y + b1);
                if (reg == 0) {
                    *(float2*)&qs[(size_t)row * 2 * HC + c] = o;
                } else if (reg == 3) {
                    *(float2*)&qs[(size_t)row * 2 * HC + HC + c] = o;
                } else {
                    int h  = c / C;
                    int ch = c - h * C;
                    size_t base = ((size_t)row * H + h) * 2 * C
                                + (ch >> 2) * 8 + (ch & 3) + (reg == 2 ? 4 : 0);
                    *(__half2*)&kv[base] = __float22half2_rn(o);
                }
            }
        }
    }
}

// =====================================================================
// CSR build
// =====================================================================
__global__ void zero_cnt_kernel(int* __restrict__ cnt, int n)
{
    int i = blockIdx.x * blockDim.x + threadIdx.x;
    if (i < n) cnt[i] = 0;
}

__global__ void hist_kernel(const int* __restrict__ dst, int* __restrict__ cnt, int E)
{
    int e = blockIdx.x * blockDim.x + threadIdx.x;
    if (e < E) atomicAdd(&cnt[dst[e]], 1);
}

__global__ void scan_block_kernel(const int* __restrict__ cnt,
                                  int* __restrict__ row,
                                  int* __restrict__ bsum, int n)
{
    __shared__ int sh[512];
    int t = threadIdx.x;
    int g = blockIdx.x * 512 + t;
    int v = (g < n) ? cnt[g] : 0;
    sh[t] = v;
    __syncthreads();
    #pragma unroll
    for (int off = 1; off < 512; off <<= 1) {
        int tmp = (t >= off) ? sh[t - off] : 0;
        __syncthreads();
        sh[t] += tmp;
        __syncthreads();
    }
    if (g < n) row[g] = sh[t] - v;
    if (t == 511) bsum[blockIdx.x] = sh[511];
}

__global__ void scan_bsum_kernel(const int* __restrict__ bsum,
                                 int* __restrict__ boff, int nb)
{
    __shared__ int sh[256];
    int t = threadIdx.x;
    int v = (t < nb) ? bsum[t] : 0;
    sh[t] = v;
    __syncthreads();
    #pragma unroll
    for (int off = 1; off < 256; off <<= 1) {
        int tmp = (t >= off) ? sh[t - off] : 0;
        __syncthreads();
        sh[t] += tmp;
        __syncthreads();
    }
    boff[t] = sh[t] - v;
}

__global__ void scan_add_kernel(int* __restrict__ row, const int* __restrict__ boff,
                                int* __restrict__ cur, int n)
{
    int g = blockIdx.x * blockDim.x + threadIdx.x;
    if (g < n) {
        int r = row[g] + boff[g >> 9];
        row[g] = r;
        cur[g] = r;
    }
}

__global__ void scatter_kernel(const int* __restrict__ src, const int* __restrict__ dst,
                               int* __restrict__ cur, int* __restrict__ csrc, int E)
{
    int e = blockIdx.x * blockDim.x + threadIdx.x;
    if (e < E) {
        int p = atomicAdd(&cur[dst[e]], 1);
        csrc[p] = src[e];
    }
}

// =====================================================================
// All-heads attention (layers with H*C/4 <= 64 lanes): one node per
// H*LPE active lanes; per edge ONE coalesced load of the node's full
// kv row covers all heads. 8-lane groups own one head each; no
// cross-group combine. Depth-2 edge prefetch; ex2.approx.
//   H=7,C=32: 56 lanes -> 64-thr block per node (2 warps)
//   H=4,C=32: 32 lanes -> 1 warp per node (2 nodes per block)
// =====================================================================
template <int H, int C>
__global__ void attn_mh(const float* __restrict__ qs,
                        const __half* __restrict__ kv,
                        const int* __restrict__ row,
                        const int* __restrict__ cnt,
                        const int* __restrict__ csrc,
                        float* __restrict__ dstb,
                        float scale, int relu, int Nn)
{
    constexpr int LPE = C / 4;
    constexpr int NL  = H * LPE;               // active lanes per node
    constexpr int WPN = (NL + 31) / 32;        // warps per node (1 or 2)
    constexpr int HC  = H * C;

    int tid  = threadIdx.x;
    int warp = tid >> 5;
    int lane = tid & 31;

    int n, gs;
    if (WPN == 2) { n = blockIdx.x;            gs = warp * 32 + lane; }
    else          { n = blockIdx.x * 2 + warp; gs = lane; }
    if (n >= Nn) return;
    bool active = gs < NL;

    const unsigned gmask = (((LPE < 32) ? ((1u << LPE) - 1u) : 0xffffffffu))
                           << ((lane / LPE) * LPE);

    float4 q4 = make_float4(0.f, 0.f, 0.f, 0.f);
    if (active) q4 = *(const float4*)&qs[(size_t)n * 2 * HC + gs * 4];
    float qsc = scale * 1.44269504089f;
    q4.x *= qsc; q4.y *= qsc; q4.z *= qsc; q4.w *= qsc;

    int start = row[n];
    int deg   = cnt[n];
    const int* ep = csrc + start;

    float  l = 0.f;
    float4 acc = make_float4(0.f, 0.f, 0.f, 0.f);

    if (active && deg > 0) {
        int s0 = __ldg(&ep[0]);
        uint4 raw = __ldg((const uint4*)&kv[(size_t)s0 * 2 * HC + gs * 8]);
        int s_nxt = (deg > 1) ? __ldg(&ep[1]) : 0;

        for (int e = 0; e < deg; e++) {
            uint4 cur = raw;
            if (e + 1 < deg) {
                raw = __ldg((const uint4*)&kv[(size_t)s_nxt * 2 * HC + gs * 8]);
                if (e + 2 < deg) s_nxt = __ldg(&ep[e + 2]);
            }

            float2 k01 = h2f(cur.x), k23 = h2f(cur.y);
            float2 v01 = h2f(cur.z), v23 = h2f(cur.w);

            float dot = q4.x * k01.x;
            dot = fmaf(q4.y, k01.y, dot);
            dot = fmaf(q4.z, k23.x, dot);
            dot = fmaf(q4.w, k23.y, dot);
            #pragma unroll
            for (int o = 1; o < LPE; o <<= 1)
                dot += __shfl_xor_sync(gmask, dot, o);

            float p = ex2_approx(dot);
            l += p;
            acc.x = fmaf(p, v01.x, acc.x);
            acc.y = fmaf(p, v01.y, acc.y);
            acc.z = fmaf(p, v23.x, acc.z);
            acc.w = fmaf(p, v23.y, acc.w);
        }
    }

    // each 8-lane group holds its head's full result; l identical in-group
    if (active) {
        float inv = 1.0f / (l + 1e-16f);
        float4 o4 = *(const float4*)&qs[(size_t)n * 2 * HC + HC + gs * 4];  // skip
        o4.x += acc.x * inv;
        o4.y += acc.y * inv;
        o4.z += acc.z * inv;
        o4.w += acc.w * inv;
        if (relu) {
            o4.x = fmaxf(o4.x, 0.f);
            o4.y = fmaxf(o4.y, 0.f);
            o4.z = fmaxf(o4.z, 0.f);
            o4.w = fmaxf(o4.w, 0.f);
        }
        *(float4*)&dstb[(size_t)n * HC + gs * 4] = o4;
    }
}

// =====================================================================
// Single-head attention (layer 3: H=1, C=64): LPE=16 lanes/edge,
// 2 edges in flight per warp, direct-indexed, depth-2 prefetch.
// =====================================================================
template <int LPE>
__global__ void attn_kernel(const float* __restrict__ qs,
                            const __half* __restrict__ kv,
                            const int* __restrict__ row,
                            const int* __restrict__ cnt,
                            const int* __restrict__ csrc,
                            float* __restrict__ dstb,
                            int H, float scale, int relu, int Nn)
{
    constexpr int EPW = 32 / LPE;
    constexpr int C   = LPE * 4;

    int w    = (blockIdx.x * blockDim.x + threadIdx.x) >> 5;
    int lane = threadIdx.x & 31;
    if (w >= Nn * H) return;
    int h = w / Nn;
    int n = w - h * Nn;
    const int HC = H * C;
    int sl  = lane & (LPE - 1);
    int sub = lane / LPE;
    const unsigned gmask = (((LPE < 32) ? ((1u << LPE) - 1u) : 0xffffffffu)) << (sub * LPE);

    float4 q4 = *(const float4*)&qs[(size_t)n * 2 * HC + h * C + sl * 4];
    float qsc = scale * 1.44269504089f;
    q4.x *= qsc; q4.y *= qsc; q4.z *= qsc; q4.w *= qsc;

    int start = row[n];
    int deg   = cnt[n];
    const int* ep = csrc + start;

    float  l = 0.f;
    float4 acc = make_float4(0.f, 0.f, 0.f, 0.f);

    uint4 raw = make_uint4(0u, 0u, 0u, 0u);
    int   s_nxt = 0;
    if (sub < deg) {
        int s0 = __ldg(&ep[sub]);
        raw = __ldg((const uint4*)&kv[((size_t)s0 * H + h) * 2 * C + sl * 8]);
        if (sub + EPW < deg) s_nxt = __ldg(&ep[sub + EPW]);
    }

    for (int e = sub; e < deg; e += EPW) {
        uint4 cur = raw;
        if (e + EPW < deg) {
            raw = __ldg((const uint4*)&kv[((size_t)s_nxt * H + h) * 2 * C + sl * 8]);
            if (e + 2 * EPW < deg) s_nxt = __ldg(&ep[e + 2 * EPW]);
        }

        float2 k01 = h2f(cur.x), k23 = h2f(cur.y);
        float2 v01 = h2f(cur.z), v23 = h2f(cur.w);

        float dot = q4.x * k01.x;
        dot = fmaf(q4.y, k01.y, dot);
        dot = fmaf(q4.z, k23.x, dot);
        dot = fmaf(q4.w, k23.y, dot);
        #pragma unroll
        for (int o = 1; o < LPE; o <<= 1)
            dot += __shfl_xor_sync(gmask, dot, o);

        float p = ex2_approx(dot);
        l += p;
        acc.x = fmaf(p, v01.x, acc.x);
        acc.y = fmaf(p, v01.y, acc.y);
        acc.z = fmaf(p, v23.x, acc.z);
        acc.w = fmaf(p, v23.y, acc.w);
    }

    #pragma unroll
    for (int o = LPE; o < 32; o <<= 1) {
        l     += __shfl_xor_sync(0xffffffffu, l, o);
        acc.x += __shfl_xor_sync(0xffffffffu, acc.x, o);
        acc.y += __shfl_xor_sync(0xffffffffu, acc.y, o);
        acc.z += __shfl_xor_sync(0xffffffffu, acc.z, o);
        acc.w += __shfl_xor_sync(0xffffffffu, acc.w, o);
    }

    float inv = 1.0f / (l + 1e-16f);
    if (lane < LPE) {
        float4 o4 = *(const float4*)&qs[(size_t)n * 2 * HC + HC + h * C + lane * 4];
        o4.x += acc.x * inv;
        o4.y += acc.y * inv;
        o4.z += acc.z * inv;
        o4.w += acc.w * inv;
        if (relu) {
            o4.x = fmaxf(o4.x, 0.f);
            o4.y = fmaxf(o4.y, 0.f);
            o4.z = fmaxf(o4.z, 0.f);
            o4.w = fmaxf(o4.w, 0.f);
        }
        *(float4*)&dstb[(size_t)n * HC + h * C + lane * 4] = o4;
    }
}

// =====================================================================
// Host-side orchestration
// =====================================================================
static void* sym_addr(const void* symbol)
{
    void* p = nullptr;
    cudaGetSymbolAddress(&p, symbol);
    return p;
}

extern "C" void kernel_launch(void* const* d_in, const int* in_sizes, int n_in,
                              void* d_out, int out_size)
{
    const float* x  = (const float*)d_in[0];
    const int*   ei = (const int*)d_in[1];
    const int N = in_sizes[0] / 64;
    const int E = in_sizes[1] / 2;
    const int* src = ei;
    const int* dst = ei + E;

    const float* W[24];
    for (int i = 0; i < 24; i++) W[i] = (const float*)d_in[2 + i];

    float*  qs  = (float*)sym_addr(g_qs);
    __half* kv  = (__half*)sym_addr(g_kv);
    float* h1   = (float*)sym_addr(g_h1);
    float* h2   = (float*)sym_addr(g_h2);
    float* wp   = (float*)sym_addr(g_wp);
    float* bp   = (float*)sym_addr(g_bp);
    int*   cnt  = (int*)sym_addr(g_cnt);
    int*   row  = (int*)sym_addr(g_row);
    int*   cur  = (int*)sym_addr(g_cur);
    int*   bsum = (int*)sym_addr(g_bsum);
    int*   boff = (int*)sym_addr(g_boff);
    int*   csrc = (int*)sym_addr(g_csrc);
    float* out  = (float*)d_out;

    float* wp1 = wp;            float* bp1 = bp;
    float* wp2 = wp + 57344;    float* bp2 = bp + 896;
    float* wp3 = wp + 172032;   float* bp3 = bp + 1408;

    int nscan = (N + 511) / 512;

    // launch order keeps layer-1 GEMM in the ncu capture slot (#4)
    pack_w<<<(64 * 896 + 255) / 256, 256>>>(W[0], W[2], W[4], W[6], W[1], W[3], W[5], W[7],
                                            wp1, bp1, 64, 224);
    zero_cnt_kernel<<<(N + 255) / 256, 256>>>(cnt, N);
    hist_kernel<<<(E + 255) / 256, 256>>>(dst, cnt, E);

    // Layer 1 fused GEMM: [N,64] x [64,896]
    {
        dim3 grid(896 / 128, (N + 127) / 128);
        gemm_bf16s<64, 224, 32><<<grid, 256>>>(x, wp1, bp1, qs, kv, N);
    }

    scan_block_kernel<<<nscan, 512>>>(cnt, row, bsum, N);
    scan_bsum_kernel<<<1, 256>>>(bsum, boff, nscan);
    scan_add_kernel<<<(N + 255) / 256, 256>>>(row, boff, cur, N);
    scatter_kernel<<<(E + 255) / 256, 256>>>(src, dst, cur, csrc, E);
    pack_w<<<(224 * 512 + 255) / 256, 256>>>(W[8], W[10], W[12], W[14], W[9], W[11], W[13], W[15],
                                             wp2, bp2, 224, 128);
    pack_w<<<(128 * 256 + 255) / 256, 256>>>(W[16], W[18], W[20], W[22], W[17], W[19], W[21], W[23],
                                             wp3, bp3, 128, 64);

    // Layer 1 attn: H=7, C=32, all-heads (1 node / 64-thr block), relu -> h1
    attn_mh<7, 32><<<N, 64>>>(qs, kv, row, cnt, csrc, h1,
                              1.0f / sqrtf(32.f), 1, N);

    // Layer 2: [N,224] x [224,512]
    {
        dim3 grid(512 / 128, (N + 127) / 128);
        gemm_bf16s<224, 128, 32><<<grid, 256>>>(h1, wp2, bp2, qs, kv, N);
    }
    // Layer 2 attn: H=4, C=32, all-heads (2 nodes / 64-thr block), relu -> h2
    attn_mh<4, 32><<<(N + 1) / 2, 64>>>(qs, kv, row, cnt, csrc, h2,
                                        1.0f / sqrtf(32.f), 1, N);

    // Layer 3: [N,128] x [128,256]
    {
        dim3 grid(256 / 128, (N + 127) / 128);
        gemm_bf16s<128, 64, 64><<<grid, 256>>>(h2, wp3, bp3, qs, kv, N);
    }
    // Layer 3 attn: H=1, C=64, 2 edges/warp -> d_out
    {
        int blocks = (N * 32 + 63) / 64;
        attn_kernel<16><<<blocks, 64>>>(qs, kv, row, cnt, csrc, out,
                                        1, 1.0f / sqrtf(64.f), 0, N);
    }
}